// round 9
// baseline (speedup 1.0000x reference)
#include <cuda_runtime.h>
#include <cuda_bf16.h>
#include <math.h>
#include <stdint.h>

// ---------------------------------------------------------------------------
// LSTMDecoder via mma.sync bf16 (tcgen05 unavailable: harness targets
// compute_103 without the 'a' suffix).
//
// lstm_mma: 128 persistent CTAs x 512 threads. Per CTA: 8 hidden units
// (32 gate rows x 64 batch). W_hh slice resident in SMEM (132KB) all steps.
// Per step: 8 K-chunks of h streamed via cp.async double-buffer; 16 warps =
// 2(mi) x 4(nj) x 2(kw K-split); 3-pass hi/lo bf16 m16n8k16, fp32 regs;
// cross-kw reduce in SMEM; epilogue 1 (b,u) per thread with prefetched
// input-projection gathers; flag-array global barrier (1 release store +
// parallel polling of 128 distinct flags).
// ---------------------------------------------------------------------------

#define Bz    64
#define Hh    1024
#define Ll    128
#define G4    4096
#define KDIM  512
#define NCTA  128
#define TPB   512

__device__ float g_rp[256 * 4096];
__device__ float g_tp[256 * 4096];
__device__ float g_xp[64 * 4096];
__device__ __align__(16) unsigned char g_wimg[128u * 132096u];
__device__ __align__(16) unsigned short g_h16[2][131072];
__device__ unsigned int g_flags[NCTA];
__device__ int          g_is64;

// ---- smem layout (bytes, dynamic) ----
#define OFF_WHI 0
#define OFF_WLO 66048
#define OFF_HB0 132096
#define OFF_HB1 166912
#define SMEM_BYTES 201728
#define W_STRIDE 2064       // 1024 bf16 * 2B + 16 pad
#define H_STRIDE 272        // 128 bf16 * 2B + 16 pad
#define HB_LO    17408      // 64 rows * 272

// ---- helpers ---------------------------------------------------------------
__device__ __forceinline__ uint32_t smem_to_u32(const void* smem_ptr) {
    uint32_t addr;
    asm("{ .reg .u64 tmp; cvta.to.shared.u64 tmp, %1; cvt.u32.u64 %0, tmp; }"
        : "=r"(addr) : "l"(smem_ptr));
    return addr;
}

#define CP_ASYNC16(dst, src) \
    asm volatile("cp.async.cg.shared.global [%0], [%1], 16;" \
                 :: "r"((uint32_t)(dst)), "l"(src) : "memory")
#define CP_COMMIT() \
    asm volatile("cp.async.commit_group;" ::: "memory")
#define CP_WAIT0() \
    asm volatile("cp.async.wait_group 0;" ::: "memory")

__device__ __forceinline__ void ldsm4(uint32_t& r0, uint32_t& r1,
                                      uint32_t& r2, uint32_t& r3,
                                      uint32_t addr) {
    asm volatile(
        "ldmatrix.sync.aligned.m8n8.x4.shared.b16 {%0, %1, %2, %3}, [%4];"
        : "=r"(r0), "=r"(r1), "=r"(r2), "=r"(r3)
        : "r"(addr));
}

__device__ __forceinline__ void mma_bf16(float& d0, float& d1, float& d2, float& d3,
                                         uint32_t a0, uint32_t a1, uint32_t a2, uint32_t a3,
                                         uint32_t b0, uint32_t b1) {
    asm volatile(
        "mma.sync.aligned.m16n8k16.row.col.f32.bf16.bf16.f32 "
        "{%0, %1, %2, %3}, {%4, %5, %6, %7}, {%8, %9}, {%0, %1, %2, %3};"
        : "+f"(d0), "+f"(d1), "+f"(d2), "+f"(d3)
        : "r"(a0), "r"(a1), "r"(a2), "r"(a3), "r"(b0), "r"(b1));
}

__device__ __forceinline__ unsigned short bfbits(float v) {
    __nv_bfloat16 t = __float2bfloat16(v);
    return *(unsigned short*)&t;
}
__device__ __forceinline__ float bf2f(unsigned short b) {
    __nv_bfloat16 t = *(__nv_bfloat16*)&b;
    return __bfloat162float(t);
}
__device__ __forceinline__ float sigf(float x) {
    return 1.0f / (1.0f + __expf(-x));
}

// ---------------------------------------------------------------------------
// fused_proj: tables + flag reset + pa dtype sniff. grid (64,4,3), block 256.
// ---------------------------------------------------------------------------
__global__ void fused_proj(const float* __restrict__ rule,
                           const float* __restrict__ toke,
                           const float* __restrict__ x,
                           const float* __restrict__ Wih,
                           const float* __restrict__ b1,
                           const float* __restrict__ b2,
                           const int*   __restrict__ pa32)
{
    const int z = blockIdx.z;
    const float* E;
    float* Out;
    int M;
    int colOff;
    int addBias = 0;
    if (z == 0)      { E = rule; Out = g_rp; M = 256; colOff = 512; }
    else if (z == 1) { E = toke; Out = g_tp; M = 256; colOff = 512; }
    else             { E = x;    Out = g_xp; M = 64;  colOff = 0; addBias = 1; }

    if (z == 2 && blockIdx.x == 0 && blockIdx.y == 0) {
        __shared__ int any_nz;
        if (threadIdx.x == 0) { any_nz = 0; }
        if (threadIdx.x < NCTA) g_flags[threadIdx.x] = 0u;
        __syncthreads();
        if (threadIdx.x < 256 && pa32[threadIdx.x * 2 + 1] != 0)
            atomicAdd(&any_nz, 1);
        __syncthreads();
        if (threadIdx.x == 0) g_is64 = (any_nz == 0) ? 1 : 0;
    }
    if (blockIdx.y * 64 >= M) return;

    __shared__ float Es[64][17];
    __shared__ float Ws[64][17];

    const int i0 = blockIdx.y * 64;
    const int j0 = blockIdx.x * 64;
    const int t  = threadIdx.x;
    const int ty = t >> 4;
    const int tx = t & 15;

    float acc[4][4];
#pragma unroll
    for (int i = 0; i < 4; i++)
#pragma unroll
        for (int j = 0; j < 4; j++) acc[i][j] = 0.f;

    const int ii = t >> 2;
    const int a4 = (t & 3) * 4;

    for (int a0 = 0; a0 < KDIM; a0 += 16) {
        float4 ev = make_float4(0.f, 0.f, 0.f, 0.f);
        if (i0 + ii < M)
            ev = *(const float4*)(E + (size_t)(i0 + ii) * KDIM + a0 + a4);
        Es[ii][a4 + 0] = ev.x;
        Es[ii][a4 + 1] = ev.y;
        Es[ii][a4 + 2] = ev.z;
        Es[ii][a4 + 3] = ev.w;

        float4 wv = *(const float4*)(Wih + (size_t)(j0 + ii) * 1024 + colOff + a0 + a4);
        Ws[ii][a4 + 0] = wv.x;
        Ws[ii][a4 + 1] = wv.y;
        Ws[ii][a4 + 2] = wv.z;
        Ws[ii][a4 + 3] = wv.w;
        __syncthreads();

#pragma unroll
        for (int aa = 0; aa < 16; aa++) {
            float av[4];
            float bv[4];
#pragma unroll
            for (int r2 = 0; r2 < 4; r2++) av[r2] = Es[ty * 4 + r2][aa];
#pragma unroll
            for (int r2 = 0; r2 < 4; r2++) bv[r2] = Ws[tx * 4 + r2][aa];
#pragma unroll
            for (int i = 0; i < 4; i++)
#pragma unroll
                for (int j = 0; j < 4; j++) acc[i][j] = fmaf(av[i], bv[j], acc[i][j]);
        }
        __syncthreads();
    }

#pragma unroll
    for (int i = 0; i < 4; i++) {
        int gi = i0 + ty * 4 + i;
        if (gi >= M) continue;
#pragma unroll
        for (int j = 0; j < 4; j++) {
            int gj = j0 + tx * 4 + j;
            float v = acc[i][j];
            if (addBias) v += b1[gj] + b2[gj];
            Out[(size_t)gi * G4 + gj] = v;
        }
    }
}

// ---------------------------------------------------------------------------
// prep_w: bake W_hh into per-CTA bf16 hi/lo images (SMEM layout, stride 2064).
// ---------------------------------------------------------------------------
__global__ void prep_w(const float* __restrict__ Whh)
{
    const int id   = blockIdx.x * 256 + threadIdx.x;
    const int g    = id >> 10;
    const int r    = (id >> 5) & 31;
    const int kseg = id & 31;
    const int k0   = kseg * 32;
    const int gate = r >> 3;
    const int u    = r & 7;

    const float* src = Whh + (size_t)(gate * 1024 + g * 8 + u) * 1024 + k0;
    unsigned char* dhi = g_wimg + (size_t)g * 132096 + r * W_STRIDE + k0 * 2;
    unsigned char* dlo = dhi + 66048;

#pragma unroll
    for (int j = 0; j < 4; j++) {
        float4 va = *(const float4*)(src + j * 8);
        float4 vb = *(const float4*)(src + j * 8 + 4);
        float v[8];
        v[0] = va.x; v[1] = va.y; v[2] = va.z; v[3] = va.w;
        v[4] = vb.x; v[5] = vb.y; v[6] = vb.z; v[7] = vb.w;
        unsigned int hw[4];
        unsigned int lw[4];
#pragma unroll
        for (int q = 0; q < 4; q++) {
            unsigned short h0 = bfbits(v[2 * q]);
            unsigned short l0 = bfbits(v[2 * q] - bf2f(h0));
            unsigned short h1 = bfbits(v[2 * q + 1]);
            unsigned short l1 = bfbits(v[2 * q + 1] - bf2f(h1));
            hw[q] = (unsigned)h0 | ((unsigned)h1 << 16);
            lw[q] = (unsigned)l0 | ((unsigned)l1 << 16);
        }
        *(uint4*)(dhi + j * 16) = make_uint4(hw[0], hw[1], hw[2], hw[3]);
        *(uint4*)(dlo + j * 16) = make_uint4(lw[0], lw[1], lw[2], lw[3]);
    }
}

// ---------------------------------------------------------------------------
// prep_h0: bake initial h into g_h16 parity 0.
// ---------------------------------------------------------------------------
__global__ void prep_h0(const float* __restrict__ h0)
{
    const int id = blockIdx.x * 256 + threadIdx.x;
    if (id >= 2048) return;
    const int b    = id >> 5;
    const int kseg = id & 31;
    const int k0   = kseg * 32;

    const float* src = h0 + (size_t)b * 1024 + k0;
    unsigned short* dhi = &g_h16[0][b * 1024 + k0];
    unsigned short* dlo = dhi + 65536;

#pragma unroll
    for (int j = 0; j < 4; j++) {
        float4 va = *(const float4*)(src + j * 8);
        float4 vb = *(const float4*)(src + j * 8 + 4);
        float v[8];
        v[0] = va.x; v[1] = va.y; v[2] = va.z; v[3] = va.w;
        v[4] = vb.x; v[5] = vb.y; v[6] = vb.z; v[7] = vb.w;
        unsigned int hw[4];
        unsigned int lw[4];
#pragma unroll
        for (int q = 0; q < 4; q++) {
            unsigned short h0b = bfbits(v[2 * q]);
            unsigned short l0b = bfbits(v[2 * q] - bf2f(h0b));
            unsigned short h1b = bfbits(v[2 * q + 1]);
            unsigned short l1b = bfbits(v[2 * q + 1] - bf2f(h1b));
            hw[q] = (unsigned)h0b | ((unsigned)h1b << 16);
            lw[q] = (unsigned)l0b | ((unsigned)l1b << 16);
        }
        *(uint4*)(dhi + j * 8) = make_uint4(hw[0], hw[1], hw[2], hw[3]);
        *(uint4*)(dlo + j * 8) = make_uint4(lw[0], lw[1], lw[2], lw[3]);
    }
}

// ---------------------------------------------------------------------------
// lstm_mma: persistent 128-CTA x 512-thread mma.sync recurrence.
// ---------------------------------------------------------------------------
__global__ void __launch_bounds__(TPB, 1)
lstm_mma(const float* __restrict__ c0,
         const void*  __restrict__ pa_raw,
         const float* __restrict__ tok_embed,
         const float* __restrict__ W_ih,
         float* __restrict__ out)
{
    extern __shared__ unsigned char smem[];
    const uint32_t sb = smem_to_u32(smem);
    const int tid  = threadIdx.x;
    const int wid  = tid >> 5;
    const int lane = tid & 31;
    const int g    = blockIdx.x;
    const int is64 = g_is64;

    // ---- one-time W image copy into SMEM ----
    {
        const unsigned char* wsrc = g_wimg + (size_t)g * 132096;
        for (int i = tid; i < 8256; i += TPB) {
            CP_ASYNC16(sb + OFF_WHI + i * 16, wsrc + (size_t)i * 16);
        }
        CP_COMMIT();
        CP_WAIT0();
        __syncthreads();
    }

    // ---- epilogue identity: 1 (b, unit) per thread ----
    const int b_e = tid & 63;
    const int uh  = tid >> 6;          // 0..7
    const int kg  = g * 8 + uh;
    float cst = c0[(size_t)b_e * Hh + kg];
    float hst = 0.f;

    // ---- GEMM identity: 16 warps = kw(2) x mi(2) x nj(4) ----
    const int kw = wid >> 3;
    const int mi = (wid >> 2) & 1;
    const int nj = wid & 3;
    const uint32_t aoff = (uint32_t)((mi * 16 + (lane & 15)) * W_STRIDE
                                     + ((lane & 16) ? 16 : 0));
    const uint32_t boff = (uint32_t)((nj * 16 + (lane & 15)) * H_STRIDE
                                     + ((lane & 16) ? 16 : 0));

    // staging identity: row = tid>>3 (0..63), seg = tid&7 (16 kk each)
    const int sg_row = tid >> 3;
    const int sg_seg = tid & 7;

    float* smemD = (float*)(smem + OFF_HB0);   // 2 x 32 x 65 fp32 overlay

#pragma unroll 1
    for (int l = 0; l < Ll; l++) {
        const unsigned short* hsrc = &g_h16[l & 1][0];

        // prologue: issue chunk 0 into HB0
        {
            const unsigned short* srcH = hsrc + sg_row * 1024 + sg_seg * 16;
            const uint32_t dstH = sb + OFF_HB0 + sg_row * H_STRIDE + sg_seg * 32;
            CP_ASYNC16(dstH,              srcH);
            CP_ASYNC16(dstH + 16,         srcH + 8);
            CP_ASYNC16(dstH + HB_LO,      srcH + 65536);
            CP_ASYNC16(dstH + HB_LO + 16, srcH + 65536 + 8);
            CP_COMMIT();
        }

        // ---- prefetch input-projection gathers (independent of GEMM) ----
        float xg[4];
        {
            const size_t pidx = ((size_t)l * Bz + b_e) * 3;
            long long ridx;
            long long tidx;
            if (is64) {
                const long long* pp = (const long long*)pa_raw;
                ridx = pp[pidx];
                tidx = pp[pidx + 1];
            } else {
                const int* pp = (const int*)pa_raw;
                ridx = (long long)pp[pidx];
                tidx = (long long)pp[pidx + 1];
            }
#pragma unroll
            for (int gt = 0; gt < 4; gt++) {
                const int gidx = gt * 1024 + kg;
                float v = g_xp[(size_t)b_e * G4 + gidx];
                if (ridx >= 0 && ridx < 256) {
                    v += g_rp[(size_t)ridx * G4 + gidx];
                }
                if (tidx >= 0 && tidx < 256) {
                    v += g_tp[(size_t)tidx * G4 + gidx];
                } else if (tidx >= 256 && tidx < 32000) {
                    const float* te = tok_embed + (size_t)tidx * KDIM;
                    const float* wa = W_ih + (size_t)(gt * 1024 + kg) * 1024 + 512;
                    float d = 0.f;
                    for (int a = 0; a < KDIM; a++) {
                        d = fmaf(te[a], wa[a], d);
                    }
                    v += d;
                }
                xg[gt] = v;
            }
        }

        float acc[8];
#pragma unroll
        for (int i = 0; i < 8; i++) acc[i] = 0.f;

#pragma unroll 1
        for (int c = 0; c < 8; c++) {
            CP_WAIT0();
            __syncthreads();
            if (c < 7) {
                const unsigned short* srcH = hsrc + sg_row * 1024 + (c + 1) * 128 + sg_seg * 16;
                const uint32_t hb = (c & 1) ? OFF_HB0 : OFF_HB1;
                const uint32_t dstH = sb + hb + sg_row * H_STRIDE + sg_seg * 32;
                CP_ASYNC16(dstH,              srcH);
                CP_ASYNC16(dstH + 16,         srcH + 8);
                CP_ASYNC16(dstH + HB_LO,      srcH + 65536);
                CP_ASYNC16(dstH + HB_LO + 16, srcH + 65536 + 8);
                CP_COMMIT();
            }

            const uint32_t hb   = (c & 1) ? OFF_HB1 : OFF_HB0;
            const uint32_t bHi  = sb + hb + boff + kw * 128;          // kw: ks 4..7 -> +4*32
            const uint32_t bLo  = bHi + HB_LO;
            const uint32_t aHiB = sb + OFF_WHI + aoff + c * 256 + kw * 128;
            const uint32_t aLoB = aHiB + 66048;

#pragma unroll
            for (int ks = 0; ks < 4; ks++) {
                uint32_t ah0, ah1, ah2, ah3;
                uint32_t al0, al1, al2, al3;
                uint32_t bh0, bh1, bh2, bh3;
                uint32_t bl0, bl1, bl2, bl3;
                ldsm4(ah0, ah1, ah2, ah3, aHiB + ks * 32);
                ldsm4(bh0, bh1, bh2, bh3, bHi + ks * 32);
                ldsm4(al0, al1, al2, al3, aLoB + ks * 32);
                ldsm4(bl0, bl1, bl2, bl3, bLo + ks * 32);
                mma_bf16(acc[0], acc[1], acc[2], acc[3], ah0, ah1, ah2, ah3, bh0, bh2);
                mma_bf16(acc[4], acc[5], acc[6], acc[7], ah0, ah1, ah2, ah3, bh1, bh3);
                mma_bf16(acc[0], acc[1], acc[2], acc[3], ah0, ah1, ah2, ah3, bl0, bl2);
                mma_bf16(acc[4], acc[5], acc[6], acc[7], ah0, ah1, ah2, ah3, bl1, bl3);
                mma_bf16(acc[0], acc[1], acc[2], acc[3], al0, al1, al2, al3, bh0, bh2);
                mma_bf16(acc[4], acc[5], acc[6], acc[7], al0, al1, al2, al3, bh1, bh3);
            }
        }
        __syncthreads();   // computes done; HB0/HB1 free for D overlay

        // ---- write D fragments to smemD[kw][32][65] ----
        {
            const int lr = lane >> 2;
            const int lc = (lane & 3) * 2;
            const int row0 = mi * 16 + lr;
            float* dk = smemD + kw * 2080;
#pragma unroll
            for (int s = 0; s < 2; s++) {
                const int col = nj * 16 + s * 8 + lc;
                dk[row0 * 65 + col]           = acc[s * 4 + 0];
                dk[row0 * 65 + col + 1]       = acc[s * 4 + 1];
                dk[(row0 + 8) * 65 + col]     = acc[s * 4 + 2];
                dk[(row0 + 8) * 65 + col + 1] = acc[s * 4 + 3];
            }
        }
        __syncthreads();

        // ---- epilogue: 1 (b, u) per thread ----
        {
            unsigned short* hdst = &g_h16[(l + 1) & 1][0];
            float gv[4];
#pragma unroll
            for (int gt = 0; gt < 4; gt++) {
                const int row = gt * 8 + uh;
                float pre = smemD[row * 65 + b_e] + smemD[2080 + row * 65 + b_e];
                gv[gt] = pre + xg[gt];
            }
            const float c1 = sigf(gv[1]) * cst + sigf(gv[0]) * tanhf(gv[2]);
            const float h1 = sigf(gv[3]) * tanhf(c1);
            cst = c1;
            hst = h1;
            out[((size_t)l * Bz + b_e) * Hh + kg] = h1;

            unsigned short hh = bfbits(h1);
            unsigned short hl = bfbits(h1 - bf2f(hh));
            hdst[b_e * 1024 + kg]         = hh;
            hdst[65536 + b_e * 1024 + kg] = hl;
        }

        // ---- device-wide barrier: flag array, parallel polling ----
        __threadfence();
        __syncthreads();
        if (tid == 0) {
            *(volatile unsigned int*)&g_flags[g] = (unsigned)(l + 1);
        }
        if (tid < NCTA) {
            while (*(volatile unsigned int*)&g_flags[tid] < (unsigned)(l + 1)) {
                __nanosleep(32);
            }
        }
        __threadfence();
        __syncthreads();
    }

    // ---- final h_n, c_n ----
    {
        const size_t base_hn = (size_t)Ll * Bz * Hh;
        const size_t base_cn = base_hn + (size_t)Bz * Hh;
        out[base_hn + (size_t)b_e * Hh + kg] = hst;
        out[base_cn + (size_t)b_e * Hh + kg] = cst;
    }
}

// ---------------------------------------------------------------------------
extern "C" void kernel_launch(void* const* d_in, const int* in_sizes, int n_in,
                              void* d_out, int out_size)
{
    const float* x    = (const float*)d_in[0];
    const void*  pa   = (const void*)d_in[1];
    // d_in[2] = mask (unused by the reference computation)
    const float* h0   = (const float*)d_in[3];
    const float* c0   = (const float*)d_in[4];
    const float* rule = (const float*)d_in[5];
    const float* toke = (const float*)d_in[6];
    const float* Wih  = (const float*)d_in[7];
    const float* Whh  = (const float*)d_in[8];
    const float* bih  = (const float*)d_in[9];
    const float* bhh  = (const float*)d_in[10];
    float* out = (float*)d_out;

    fused_proj<<<dim3(64, 4, 3), 256>>>(rule, toke, x, Wih, bih, bhh,
                                        (const int*)pa);
    prep_w<<<512, 256>>>(Whh);
    prep_h0<<<8, 256>>>(h0);

    cudaFuncSetAttribute(lstm_mma,
                         cudaFuncAttributeMaxDynamicSharedMemorySize,
                         SMEM_BYTES);
    lstm_mma<<<NCTA, TPB, SMEM_BYTES>>>(c0, pa, toke, Wih, out);
}

// round 10
// speedup vs baseline: 1.0330x; 1.0330x over previous
#include <cuda_runtime.h>
#include <cuda_bf16.h>
#include <math.h>
#include <stdint.h>

// ---------------------------------------------------------------------------
// LSTMDecoder via mma.sync bf16 (tcgen05 unavailable: harness targets
// compute_103 without the 'a' suffix).
//
// lstm_mma: 128 persistent CTAs x 256 threads (R8 structure). Per CTA: 8
// hidden units (32 gate rows x 64 batch). W_hh slice resident in SMEM (132KB)
// all 128 steps. Per step: 8 K-chunks of h streamed via cp.async double
// buffer; 8 warps = 2(mi) x 4(nj); 3-pass hi/lo bf16 m16n8k16, fp32 regs.
// R10 changes vs R8: flag-array barrier, xg gather prefetch at step start,
// epilogue ownership remap (unit-fastest -> coalesced epilogue streams).
// ---------------------------------------------------------------------------

#define Bz    64
#define Hh    1024
#define Ll    128
#define G4    4096
#define KDIM  512
#define NCTA  128
#define TPB   256

__device__ float g_rp[256 * 4096];
__device__ float g_tp[256 * 4096];
__device__ float g_xp[64 * 4096];
__device__ __align__(16) unsigned char g_wimg[128u * 132096u];
__device__ __align__(16) unsigned short g_h16[2][131072];
__device__ unsigned int g_flags[NCTA];
__device__ int          g_is64;

// ---- smem layout (bytes, dynamic) ----
#define OFF_WHI 0
#define OFF_WLO 66048
#define OFF_HB0 132096
#define OFF_HB1 166912
#define SMEM_BYTES 201728
#define W_STRIDE 2064       // 1024 bf16 * 2B + 16 pad
#define H_STRIDE 272        // 128 bf16 * 2B + 16 pad
#define HB_LO    17408      // 64 rows * 272

// ---- helpers ---------------------------------------------------------------
__device__ __forceinline__ uint32_t smem_to_u32(const void* smem_ptr) {
    uint32_t addr;
    asm("{ .reg .u64 tmp; cvta.to.shared.u64 tmp, %1; cvt.u32.u64 %0, tmp; }"
        : "=r"(addr) : "l"(smem_ptr));
    return addr;
}

#define CP_ASYNC16(dst, src) \
    asm volatile("cp.async.cg.shared.global [%0], [%1], 16;" \
                 :: "r"((uint32_t)(dst)), "l"(src) : "memory")
#define CP_COMMIT() \
    asm volatile("cp.async.commit_group;" ::: "memory")
#define CP_WAIT0() \
    asm volatile("cp.async.wait_group 0;" ::: "memory")

__device__ __forceinline__ void ldsm4(uint32_t& r0, uint32_t& r1,
                                      uint32_t& r2, uint32_t& r3,
                                      uint32_t addr) {
    asm volatile(
        "ldmatrix.sync.aligned.m8n8.x4.shared.b16 {%0, %1, %2, %3}, [%4];"
        : "=r"(r0), "=r"(r1), "=r"(r2), "=r"(r3)
        : "r"(addr));
}

__device__ __forceinline__ void mma_bf16(float& d0, float& d1, float& d2, float& d3,
                                         uint32_t a0, uint32_t a1, uint32_t a2, uint32_t a3,
                                         uint32_t b0, uint32_t b1) {
    asm volatile(
        "mma.sync.aligned.m16n8k16.row.col.f32.bf16.bf16.f32 "
        "{%0, %1, %2, %3}, {%4, %5, %6, %7}, {%8, %9}, {%0, %1, %2, %3};"
        : "+f"(d0), "+f"(d1), "+f"(d2), "+f"(d3)
        : "r"(a0), "r"(a1), "r"(a2), "r"(a3), "r"(b0), "r"(b1));
}

__device__ __forceinline__ unsigned short bfbits(float v) {
    __nv_bfloat16 t = __float2bfloat16(v);
    return *(unsigned short*)&t;
}
__device__ __forceinline__ float bf2f(unsigned short b) {
    __nv_bfloat16 t = *(__nv_bfloat16*)&b;
    return __bfloat162float(t);
}
__device__ __forceinline__ float sigf(float x) {
    return 1.0f / (1.0f + __expf(-x));
}

// ---------------------------------------------------------------------------
// fused_proj: tables + flag reset + pa dtype sniff. grid (64,4,3), block 256.
// ---------------------------------------------------------------------------
__global__ void fused_proj(const float* __restrict__ rule,
                           const float* __restrict__ toke,
                           const float* __restrict__ x,
                           const float* __restrict__ Wih,
                           const float* __restrict__ b1,
                           const float* __restrict__ b2,
                           const int*   __restrict__ pa32)
{
    const int z = blockIdx.z;
    const float* E;
    float* Out;
    int M;
    int colOff;
    int addBias = 0;
    if (z == 0)      { E = rule; Out = g_rp; M = 256; colOff = 512; }
    else if (z == 1) { E = toke; Out = g_tp; M = 256; colOff = 512; }
    else             { E = x;    Out = g_xp; M = 64;  colOff = 0; addBias = 1; }

    if (z == 2 && blockIdx.x == 0 && blockIdx.y == 0) {
        __shared__ int any_nz;
        if (threadIdx.x == 0) { any_nz = 0; }
        if (threadIdx.x < NCTA) g_flags[threadIdx.x] = 0u;
        __syncthreads();
        if (threadIdx.x < 256 && pa32[threadIdx.x * 2 + 1] != 0)
            atomicAdd(&any_nz, 1);
        __syncthreads();
        if (threadIdx.x == 0) g_is64 = (any_nz == 0) ? 1 : 0;
    }
    if (blockIdx.y * 64 >= M) return;

    __shared__ float Es[64][17];
    __shared__ float Ws[64][17];

    const int i0 = blockIdx.y * 64;
    const int j0 = blockIdx.x * 64;
    const int t  = threadIdx.x;
    const int ty = t >> 4;
    const int tx = t & 15;

    float acc[4][4];
#pragma unroll
    for (int i = 0; i < 4; i++)
#pragma unroll
        for (int j = 0; j < 4; j++) acc[i][j] = 0.f;

    const int ii = t >> 2;
    const int a4 = (t & 3) * 4;

    for (int a0 = 0; a0 < KDIM; a0 += 16) {
        float4 ev = make_float4(0.f, 0.f, 0.f, 0.f);
        if (i0 + ii < M)
            ev = *(const float4*)(E + (size_t)(i0 + ii) * KDIM + a0 + a4);
        Es[ii][a4 + 0] = ev.x;
        Es[ii][a4 + 1] = ev.y;
        Es[ii][a4 + 2] = ev.z;
        Es[ii][a4 + 3] = ev.w;

        float4 wv = *(const float4*)(Wih + (size_t)(j0 + ii) * 1024 + colOff + a0 + a4);
        Ws[ii][a4 + 0] = wv.x;
        Ws[ii][a4 + 1] = wv.y;
        Ws[ii][a4 + 2] = wv.z;
        Ws[ii][a4 + 3] = wv.w;
        __syncthreads();

#pragma unroll
        for (int aa = 0; aa < 16; aa++) {
            float av[4];
            float bv[4];
#pragma unroll
            for (int r2 = 0; r2 < 4; r2++) av[r2] = Es[ty * 4 + r2][aa];
#pragma unroll
            for (int r2 = 0; r2 < 4; r2++) bv[r2] = Ws[tx * 4 + r2][aa];
#pragma unroll
            for (int i = 0; i < 4; i++)
#pragma unroll
                for (int j = 0; j < 4; j++) acc[i][j] = fmaf(av[i], bv[j], acc[i][j]);
        }
        __syncthreads();
    }

#pragma unroll
    for (int i = 0; i < 4; i++) {
        int gi = i0 + ty * 4 + i;
        if (gi >= M) continue;
#pragma unroll
        for (int j = 0; j < 4; j++) {
            int gj = j0 + tx * 4 + j;
            float v = acc[i][j];
            if (addBias) v += b1[gj] + b2[gj];
            Out[(size_t)gi * G4 + gj] = v;
        }
    }
}

// ---------------------------------------------------------------------------
// prep_w: bake W_hh into per-CTA bf16 hi/lo images (SMEM layout, stride 2064).
// ---------------------------------------------------------------------------
__global__ void prep_w(const float* __restrict__ Whh)
{
    const int id   = blockIdx.x * 256 + threadIdx.x;
    const int g    = id >> 10;
    const int r    = (id >> 5) & 31;
    const int kseg = id & 31;
    const int k0   = kseg * 32;
    const int gate = r >> 3;
    const int u    = r & 7;

    const float* src = Whh + (size_t)(gate * 1024 + g * 8 + u) * 1024 + k0;
    unsigned char* dhi = g_wimg + (size_t)g * 132096 + r * W_STRIDE + k0 * 2;
    unsigned char* dlo = dhi + 66048;

#pragma unroll
    for (int j = 0; j < 4; j++) {
        float4 va = *(const float4*)(src + j * 8);
        float4 vb = *(const float4*)(src + j * 8 + 4);
        float v[8];
        v[0] = va.x; v[1] = va.y; v[2] = va.z; v[3] = va.w;
        v[4] = vb.x; v[5] = vb.y; v[6] = vb.z; v[7] = vb.w;
        unsigned int hw[4];
        unsigned int lw[4];
#pragma unroll
        for (int q = 0; q < 4; q++) {
            unsigned short h0 = bfbits(v[2 * q]);
            unsigned short l0 = bfbits(v[2 * q] - bf2f(h0));
            unsigned short h1 = bfbits(v[2 * q + 1]);
            unsigned short l1 = bfbits(v[2 * q + 1] - bf2f(h1));
            hw[q] = (unsigned)h0 | ((unsigned)h1 << 16);
            lw[q] = (unsigned)l0 | ((unsigned)l1 << 16);
        }
        *(uint4*)(dhi + j * 16) = make_uint4(hw[0], hw[1], hw[2], hw[3]);
        *(uint4*)(dlo + j * 16) = make_uint4(lw[0], lw[1], lw[2], lw[3]);
    }
}

// ---------------------------------------------------------------------------
// prep_h0: bake initial h into g_h16 parity 0.
// ---------------------------------------------------------------------------
__global__ void prep_h0(const float* __restrict__ h0)
{
    const int id = blockIdx.x * 256 + threadIdx.x;
    if (id >= 2048) return;
    const int b    = id >> 5;
    const int kseg = id & 31;
    const int k0   = kseg * 32;

    const float* src = h0 + (size_t)b * 1024 + k0;
    unsigned short* dhi = &g_h16[0][b * 1024 + k0];
    unsigned short* dlo = dhi + 65536;

#pragma unroll
    for (int j = 0; j < 4; j++) {
        float4 va = *(const float4*)(src + j * 8);
        float4 vb = *(const float4*)(src + j * 8 + 4);
        float v[8];
        v[0] = va.x; v[1] = va.y; v[2] = va.z; v[3] = va.w;
        v[4] = vb.x; v[5] = vb.y; v[6] = vb.z; v[7] = vb.w;
        unsigned int hw[4];
        unsigned int lw[4];
#pragma unroll
        for (int q = 0; q < 4; q++) {
            unsigned short h0b = bfbits(v[2 * q]);
            unsigned short l0b = bfbits(v[2 * q] - bf2f(h0b));
            unsigned short h1b = bfbits(v[2 * q + 1]);
            unsigned short l1b = bfbits(v[2 * q + 1] - bf2f(h1b));
            hw[q] = (unsigned)h0b | ((unsigned)h1b << 16);
            lw[q] = (unsigned)l0b | ((unsigned)l1b << 16);
        }
        *(uint4*)(dhi + j * 8) = make_uint4(hw[0], hw[1], hw[2], hw[3]);
        *(uint4*)(dlo + j * 8) = make_uint4(lw[0], lw[1], lw[2], lw[3]);
    }
}

// ---------------------------------------------------------------------------
// lstm_mma: persistent 128-CTA x 256-thread mma.sync recurrence.
// ---------------------------------------------------------------------------
__global__ void __launch_bounds__(TPB, 1)
lstm_mma(const float* __restrict__ c0,
         const void*  __restrict__ pa_raw,
         const float* __restrict__ tok_embed,
         const float* __restrict__ W_ih,
         float* __restrict__ out)
{
    extern __shared__ unsigned char smem[];
    const uint32_t sb = smem_to_u32(smem);
    const int tid  = threadIdx.x;
    const int wid  = tid >> 5;
    const int lane = tid & 31;
    const int g    = blockIdx.x;
    const int is64 = g_is64;

    // ---- one-time W image copy into SMEM ----
    {
        const unsigned char* wsrc = g_wimg + (size_t)g * 132096;
        for (int i = tid; i < 8256; i += TPB) {
            CP_ASYNC16(sb + OFF_WHI + i * 16, wsrc + (size_t)i * 16);
        }
        CP_COMMIT();
        CP_WAIT0();
        __syncthreads();
    }

    // ---- epilogue identity: unit-fastest for coalesced streams ----
    // thread -> (u_e = tid&7, bq = tid>>3); handles b = bq and b = bq+32
    const int u_e = tid & 7;
    const int bq  = tid >> 3;          // 0..31
    const int kg  = g * 8 + u_e;
    float cst0 = c0[(size_t)bq * Hh + kg];
    float cst1 = c0[(size_t)(bq + 32) * Hh + kg];
    float hst0 = 0.f;
    float hst1 = 0.f;

    // ---- GEMM identity: 8 warps = mi(2) x nj(4) ----
    const int mi = wid >> 2;
    const int nj = wid & 3;
    const uint32_t aoff = (uint32_t)((mi * 16 + (lane & 15)) * W_STRIDE
                                     + ((lane & 16) ? 16 : 0));
    const uint32_t boff = (uint32_t)((nj * 16 + (lane & 15)) * H_STRIDE
                                     + ((lane & 16) ? 16 : 0));

    // staging identity: row = tid>>2 (0..63), seg = tid&3 (32 kk each)
    const int sg_row = tid >> 2;
    const int sg_seg = tid & 3;

    float* smemD = (float*)(smem + OFF_HB0);   // 32 x 65 fp32 overlay

#pragma unroll 1
    for (int l = 0; l < Ll; l++) {
        const unsigned short* hsrc = &g_h16[l & 1][0];

        // prologue: issue chunk 0 into HB0
        {
            const unsigned short* srcH = hsrc + sg_row * 1024 + sg_seg * 32;
            const uint32_t dstH = sb + OFF_HB0 + sg_row * H_STRIDE + sg_seg * 64;
#pragma unroll
            for (int i = 0; i < 4; i++) {
                CP_ASYNC16(dstH + i * 16, srcH + i * 8);
                CP_ASYNC16(dstH + HB_LO + i * 16, srcH + 65536 + i * 8);
            }
            CP_COMMIT();
        }

        // ---- prefetch input-projection gathers (hide L2 under GEMM) ----
        float xg0[4];
        float xg1[4];
#pragma unroll
        for (int e = 0; e < 2; e++) {
            const int b = bq + e * 32;
            const size_t pidx = ((size_t)l * Bz + b) * 3;
            long long ridx;
            long long tidx;
            if (is64) {
                const long long* pp = (const long long*)pa_raw;
                ridx = pp[pidx];
                tidx = pp[pidx + 1];
            } else {
                const int* pp = (const int*)pa_raw;
                ridx = (long long)pp[pidx];
                tidx = (long long)pp[pidx + 1];
            }
            float* xg = e ? xg1 : xg0;
#pragma unroll
            for (int gt = 0; gt < 4; gt++) {
                const int gidx = gt * 1024 + kg;
                float v = g_xp[(size_t)b * G4 + gidx];
                if (ridx >= 0 && ridx < 256) {
                    v += g_rp[(size_t)ridx * G4 + gidx];
                }
                if (tidx >= 0 && tidx < 256) {
                    v += g_tp[(size_t)tidx * G4 + gidx];
                } else if (tidx >= 256 && tidx < 32000) {
                    const float* te = tok_embed + (size_t)tidx * KDIM;
                    const float* wa = W_ih + (size_t)gidx * 1024 + 512;
                    float d = 0.f;
                    for (int a = 0; a < KDIM; a++) {
                        d = fmaf(te[a], wa[a], d);
                    }
                    v += d;
                }
                xg[gt] = v;
            }
        }

        float acc[8];
#pragma unroll
        for (int i = 0; i < 8; i++) acc[i] = 0.f;

#pragma unroll 1
        for (int c = 0; c < 8; c++) {
            CP_WAIT0();
            __syncthreads();
            if (c < 7) {
                const unsigned short* srcH = hsrc + sg_row * 1024 + (c + 1) * 128 + sg_seg * 32;
                const uint32_t hb = (c & 1) ? OFF_HB0 : OFF_HB1;
                const uint32_t dstH = sb + hb + sg_row * H_STRIDE + sg_seg * 64;
#pragma unroll
                for (int i = 0; i < 4; i++) {
                    CP_ASYNC16(dstH + i * 16, srcH + i * 8);
                    CP_ASYNC16(dstH + HB_LO + i * 16, srcH + 65536 + i * 8);
                }
                CP_COMMIT();
            }

            const uint32_t hb   = (c & 1) ? OFF_HB1 : OFF_HB0;
            const uint32_t bHi  = sb + hb + boff;
            const uint32_t bLo  = bHi + HB_LO;
            const uint32_t aHiB = sb + OFF_WHI + aoff + c * 256;
            const uint32_t aLoB = aHiB + 66048;

#pragma unroll
            for (int ks = 0; ks < 8; ks++) {
                uint32_t ah0, ah1, ah2, ah3;
                uint32_t al0, al1, al2, al3;
                uint32_t bh0, bh1, bh2, bh3;
                uint32_t bl0, bl1, bl2, bl3;
                ldsm4(ah0, ah1, ah2, ah3, aHiB + ks * 32);
                ldsm4(bh0, bh1, bh2, bh3, bHi + ks * 32);
                ldsm4(al0, al1, al2, al3, aLoB + ks * 32);
                ldsm4(bl0, bl1, bl2, bl3, bLo + ks * 32);
                mma_bf16(acc[0], acc[1], acc[2], acc[3], ah0, ah1, ah2, ah3, bh0, bh2);
                mma_bf16(acc[4], acc[5], acc[6], acc[7], ah0, ah1, ah2, ah3, bh1, bh3);
                mma_bf16(acc[0], acc[1], acc[2], acc[3], ah0, ah1, ah2, ah3, bl0, bl2);
                mma_bf16(acc[4], acc[5], acc[6], acc[7], ah0, ah1, ah2, ah3, bl1, bl3);
                mma_bf16(acc[0], acc[1], acc[2], acc[3], al0, al1, al2, al3, bh0, bh2);
                mma_bf16(acc[4], acc[5], acc[6], acc[7], al0, al1, al2, al3, bh1, bh3);
            }
        }
        __syncthreads();   // computes done; HB0 free for D overlay

        // ---- write D fragments to smemD [32 rows][65] ----
        {
            const int lr = lane >> 2;
            const int lc = (lane & 3) * 2;
            const int row0 = mi * 16 + lr;
#pragma unroll
            for (int s = 0; s < 2; s++) {
                const int col = nj * 16 + s * 8 + lc;
                smemD[row0 * 65 + col]           = acc[s * 4 + 0];
                smemD[row0 * 65 + col + 1]       = acc[s * 4 + 1];
                smemD[(row0 + 8) * 65 + col]     = acc[s * 4 + 2];
                smemD[(row0 + 8) * 65 + col + 1] = acc[s * 4 + 3];
            }
        }
        __syncthreads();

        // ---- epilogue: 2 (b, u) pairs per thread (unit-fastest) ----
        {
            unsigned short* hdst = &g_h16[(l + 1) & 1][0];
#pragma unroll
            for (int e = 0; e < 2; e++) {
                const int b = bq + e * 32;
                const float* xg = e ? xg1 : xg0;
                float gv[4];
#pragma unroll
                for (int gt = 0; gt < 4; gt++) {
                    gv[gt] = smemD[(gt * 8 + u_e) * 65 + b] + xg[gt];
                }
                const float cprev = e ? cst1 : cst0;
                const float c1 = sigf(gv[1]) * cprev + sigf(gv[0]) * tanhf(gv[2]);
                const float h1 = sigf(gv[3]) * tanhf(c1);
                if (e) { cst1 = c1; hst1 = h1; }
                else   { cst0 = c1; hst0 = h1; }
                out[((size_t)l * Bz + b) * Hh + kg] = h1;

                unsigned short hh = bfbits(h1);
                unsigned short hl = bfbits(h1 - bf2f(hh));
                hdst[b * 1024 + kg]         = hh;
                hdst[65536 + b * 1024 + kg] = hl;
            }
        }

        // ---- device-wide barrier: flag array, parallel polling ----
        __threadfence();
        __syncthreads();
        if (tid == 0) {
            *(volatile unsigned int*)&g_flags[g] = (unsigned)(l + 1);
        }
        if (tid < NCTA) {
            while (*(volatile unsigned int*)&g_flags[tid] < (unsigned)(l + 1)) {
                __nanosleep(32);
            }
        }
        __threadfence();
        __syncthreads();
    }

    // ---- final h_n, c_n ----
    {
        const size_t base_hn = (size_t)Ll * Bz * Hh;
        const size_t base_cn = base_hn + (size_t)Bz * Hh;
        out[base_hn + (size_t)bq * Hh + kg]        = hst0;
        out[base_hn + (size_t)(bq + 32) * Hh + kg] = hst1;
        out[base_cn + (size_t)bq * Hh + kg]        = cst0;
        out[base_cn + (size_t)(bq + 32) * Hh + kg] = cst1;
    }
}

// ---------------------------------------------------------------------------
extern "C" void kernel_launch(void* const* d_in, const int* in_sizes, int n_in,
                              void* d_out, int out_size)
{
    const float* x    = (const float*)d_in[0];
    const void*  pa   = (const void*)d_in[1];
    // d_in[2] = mask (unused by the reference computation)
    const float* h0   = (const float*)d_in[3];
    const float* c0   = (const float*)d_in[4];
    const float* rule = (const float*)d_in[5];
    const float* toke = (const float*)d_in[6];
    const float* Wih  = (const float*)d_in[7];
    const float* Whh  = (const float*)d_in[8];
    const float* bih  = (const float*)d_in[9];
    const float* bhh  = (const float*)d_in[10];
    float* out = (float*)d_out;

    fused_proj<<<dim3(64, 4, 3), 256>>>(rule, toke, x, Wih, bih, bhh,
                                        (const int*)pa);
    prep_w<<<512, 256>>>(Whh);
    prep_h0<<<8, 256>>>(h0);

    cudaFuncSetAttribute(lstm_mma,
                         cudaFuncAttributeMaxDynamicSharedMemorySize,
                         SMEM_BYTES);
    lstm_mma<<<NCTA, TPB, SMEM_BYTES>>>(c0, pa, toke, Wih, out);
}

// round 11
// speedup vs baseline: 1.4521x; 1.4058x over previous
#include <cuda_runtime.h>
#include <cuda_bf16.h>
#include <math.h>
#include <stdint.h>

// ---------------------------------------------------------------------------
// LSTMDecoder via mma.sync bf16 (tcgen05 unavailable: harness targets
// compute_103 without the 'a' suffix).
//
// lstm_mma: 128 persistent CTAs x 256 threads (R8 structure, the 2519us
// baseline). Per CTA: 8 hidden units (32 gate rows x 64 batch). W_hh slice
// resident in SMEM (132KB) all 128 steps. Per step: 8 K-chunks of h streamed
// via cp.async double buffer; 8 warps = 2(mi) x 4(nj); 3-pass hi/lo bf16
// m16n8k16, fp32 regs. R11 vs R8 (two local edits only):
//   1) epilogue ownership unit-fastest (coalesced gathers/stores),
//   2) split-counter barrier (8 lines x 16 arrivals instead of 128 serialized
//      same-address atomics).
// ---------------------------------------------------------------------------

#define Bz    64
#define Hh    1024
#define Ll    128
#define G4    4096
#define KDIM  512
#define NCTA  128
#define TPB   256

__device__ float g_rp[256 * 4096];
__device__ float g_tp[256 * 4096];
__device__ float g_xp[64 * 4096];
__device__ __align__(16) unsigned char g_wimg[128u * 132096u];
__device__ __align__(16) unsigned short g_h16[2][131072];
__device__ unsigned int g_ctr8[256];   // 8 counters at stride 32 (128B apart)
__device__ int          g_is64;

// ---- smem layout (bytes, dynamic) ----
#define OFF_WHI 0
#define OFF_WLO 66048
#define OFF_HB0 132096
#define OFF_HB1 166912
#define SMEM_BYTES 201728
#define W_STRIDE 2064       // 1024 bf16 * 2B + 16 pad
#define H_STRIDE 272        // 128 bf16 * 2B + 16 pad
#define HB_LO    17408      // 64 rows * 272

// ---- helpers ---------------------------------------------------------------
__device__ __forceinline__ uint32_t smem_to_u32(const void* smem_ptr) {
    uint32_t addr;
    asm("{ .reg .u64 tmp; cvta.to.shared.u64 tmp, %1; cvt.u32.u64 %0, tmp; }"
        : "=r"(addr) : "l"(smem_ptr));
    return addr;
}

#define CP_ASYNC16(dst, src) \
    asm volatile("cp.async.cg.shared.global [%0], [%1], 16;" \
                 :: "r"((uint32_t)(dst)), "l"(src) : "memory")
#define CP_COMMIT() \
    asm volatile("cp.async.commit_group;" ::: "memory")
#define CP_WAIT0() \
    asm volatile("cp.async.wait_group 0;" ::: "memory")

__device__ __forceinline__ void ldsm4(uint32_t& r0, uint32_t& r1,
                                      uint32_t& r2, uint32_t& r3,
                                      uint32_t addr) {
    asm volatile(
        "ldmatrix.sync.aligned.m8n8.x4.shared.b16 {%0, %1, %2, %3}, [%4];"
        : "=r"(r0), "=r"(r1), "=r"(r2), "=r"(r3)
        : "r"(addr));
}

__device__ __forceinline__ void mma_bf16(float& d0, float& d1, float& d2, float& d3,
                                         uint32_t a0, uint32_t a1, uint32_t a2, uint32_t a3,
                                         uint32_t b0, uint32_t b1) {
    asm volatile(
        "mma.sync.aligned.m16n8k16.row.col.f32.bf16.bf16.f32 "
        "{%0, %1, %2, %3}, {%4, %5, %6, %7}, {%8, %9}, {%0, %1, %2, %3};"
        : "+f"(d0), "+f"(d1), "+f"(d2), "+f"(d3)
        : "r"(a0), "r"(a1), "r"(a2), "r"(a3), "r"(b0), "r"(b1));
}

__device__ __forceinline__ unsigned short bfbits(float v) {
    __nv_bfloat16 t = __float2bfloat16(v);
    return *(unsigned short*)&t;
}
__device__ __forceinline__ float bf2f(unsigned short b) {
    __nv_bfloat16 t = *(__nv_bfloat16*)&b;
    return __bfloat162float(t);
}
__device__ __forceinline__ float sigf(float x) {
    return 1.0f / (1.0f + __expf(-x));
}

// ---------------------------------------------------------------------------
// fused_proj: tables + counter reset + pa dtype sniff. grid (64,4,3), blk 256.
// ---------------------------------------------------------------------------
__global__ void fused_proj(const float* __restrict__ rule,
                           const float* __restrict__ toke,
                           const float* __restrict__ x,
                           const float* __restrict__ Wih,
                           const float* __restrict__ b1,
                           const float* __restrict__ b2,
                           const int*   __restrict__ pa32)
{
    const int z = blockIdx.z;
    const float* E;
    float* Out;
    int M;
    int colOff;
    int addBias = 0;
    if (z == 0)      { E = rule; Out = g_rp; M = 256; colOff = 512; }
    else if (z == 1) { E = toke; Out = g_tp; M = 256; colOff = 512; }
    else             { E = x;    Out = g_xp; M = 64;  colOff = 0; addBias = 1; }

    if (z == 2 && blockIdx.x == 0 && blockIdx.y == 0) {
        __shared__ int any_nz;
        if (threadIdx.x == 0) { any_nz = 0; }
        if (threadIdx.x < 8) g_ctr8[threadIdx.x * 32] = 0u;
        __syncthreads();
        if (threadIdx.x < 256 && pa32[threadIdx.x * 2 + 1] != 0)
            atomicAdd(&any_nz, 1);
        __syncthreads();
        if (threadIdx.x == 0) g_is64 = (any_nz == 0) ? 1 : 0;
    }
    if (blockIdx.y * 64 >= M) return;

    __shared__ float Es[64][17];
    __shared__ float Ws[64][17];

    const int i0 = blockIdx.y * 64;
    const int j0 = blockIdx.x * 64;
    const int t  = threadIdx.x;
    const int ty = t >> 4;
    const int tx = t & 15;

    float acc[4][4];
#pragma unroll
    for (int i = 0; i < 4; i++)
#pragma unroll
        for (int j = 0; j < 4; j++) acc[i][j] = 0.f;

    const int ii = t >> 2;
    const int a4 = (t & 3) * 4;

    for (int a0 = 0; a0 < KDIM; a0 += 16) {
        float4 ev = make_float4(0.f, 0.f, 0.f, 0.f);
        if (i0 + ii < M)
            ev = *(const float4*)(E + (size_t)(i0 + ii) * KDIM + a0 + a4);
        Es[ii][a4 + 0] = ev.x;
        Es[ii][a4 + 1] = ev.y;
        Es[ii][a4 + 2] = ev.z;
        Es[ii][a4 + 3] = ev.w;

        float4 wv = *(const float4*)(Wih + (size_t)(j0 + ii) * 1024 + colOff + a0 + a4);
        Ws[ii][a4 + 0] = wv.x;
        Ws[ii][a4 + 1] = wv.y;
        Ws[ii][a4 + 2] = wv.z;
        Ws[ii][a4 + 3] = wv.w;
        __syncthreads();

#pragma unroll
        for (int aa = 0; aa < 16; aa++) {
            float av[4];
            float bv[4];
#pragma unroll
            for (int r2 = 0; r2 < 4; r2++) av[r2] = Es[ty * 4 + r2][aa];
#pragma unroll
            for (int r2 = 0; r2 < 4; r2++) bv[r2] = Ws[tx * 4 + r2][aa];
#pragma unroll
            for (int i = 0; i < 4; i++)
#pragma unroll
                for (int j = 0; j < 4; j++) acc[i][j] = fmaf(av[i], bv[j], acc[i][j]);
        }
        __syncthreads();
    }

#pragma unroll
    for (int i = 0; i < 4; i++) {
        int gi = i0 + ty * 4 + i;
        if (gi >= M) continue;
#pragma unroll
        for (int j = 0; j < 4; j++) {
            int gj = j0 + tx * 4 + j;
            float v = acc[i][j];
            if (addBias) v += b1[gj] + b2[gj];
            Out[(size_t)gi * G4 + gj] = v;
        }
    }
}

// ---------------------------------------------------------------------------
// prep_w: bake W_hh into per-CTA bf16 hi/lo images (SMEM layout, stride 2064).
// ---------------------------------------------------------------------------
__global__ void prep_w(const float* __restrict__ Whh)
{
    const int id   = blockIdx.x * 256 + threadIdx.x;
    const int g    = id >> 10;
    const int r    = (id >> 5) & 31;
    const int kseg = id & 31;
    const int k0   = kseg * 32;
    const int gate = r >> 3;
    const int u    = r & 7;

    const float* src = Whh + (size_t)(gate * 1024 + g * 8 + u) * 1024 + k0;
    unsigned char* dhi = g_wimg + (size_t)g * 132096 + r * W_STRIDE + k0 * 2;
    unsigned char* dlo = dhi + 66048;

#pragma unroll
    for (int j = 0; j < 4; j++) {
        float4 va = *(const float4*)(src + j * 8);
        float4 vb = *(const float4*)(src + j * 8 + 4);
        float v[8];
        v[0] = va.x; v[1] = va.y; v[2] = va.z; v[3] = va.w;
        v[4] = vb.x; v[5] = vb.y; v[6] = vb.z; v[7] = vb.w;
        unsigned int hw[4];
        unsigned int lw[4];
#pragma unroll
        for (int q = 0; q < 4; q++) {
            unsigned short h0 = bfbits(v[2 * q]);
            unsigned short l0 = bfbits(v[2 * q] - bf2f(h0));
            unsigned short h1 = bfbits(v[2 * q + 1]);
            unsigned short l1 = bfbits(v[2 * q + 1] - bf2f(h1));
            hw[q] = (unsigned)h0 | ((unsigned)h1 << 16);
            lw[q] = (unsigned)l0 | ((unsigned)l1 << 16);
        }
        *(uint4*)(dhi + j * 16) = make_uint4(hw[0], hw[1], hw[2], hw[3]);
        *(uint4*)(dlo + j * 16) = make_uint4(lw[0], lw[1], lw[2], lw[3]);
    }
}

// ---------------------------------------------------------------------------
// prep_h0: bake initial h into g_h16 parity 0.
// ---------------------------------------------------------------------------
__global__ void prep_h0(const float* __restrict__ h0)
{
    const int id = blockIdx.x * 256 + threadIdx.x;
    if (id >= 2048) return;
    const int b    = id >> 5;
    const int kseg = id & 31;
    const int k0   = kseg * 32;

    const float* src = h0 + (size_t)b * 1024 + k0;
    unsigned short* dhi = &g_h16[0][b * 1024 + k0];
    unsigned short* dlo = dhi + 65536;

#pragma unroll
    for (int j = 0; j < 4; j++) {
        float4 va = *(const float4*)(src + j * 8);
        float4 vb = *(const float4*)(src + j * 8 + 4);
        float v[8];
        v[0] = va.x; v[1] = va.y; v[2] = va.z; v[3] = va.w;
        v[4] = vb.x; v[5] = vb.y; v[6] = vb.z; v[7] = vb.w;
        unsigned int hw[4];
        unsigned int lw[4];
#pragma unroll
        for (int q = 0; q < 4; q++) {
            unsigned short h0b = bfbits(v[2 * q]);
            unsigned short l0b = bfbits(v[2 * q] - bf2f(h0b));
            unsigned short h1b = bfbits(v[2 * q + 1]);
            unsigned short l1b = bfbits(v[2 * q + 1] - bf2f(h1b));
            hw[q] = (unsigned)h0b | ((unsigned)h1b << 16);
            lw[q] = (unsigned)l0b | ((unsigned)l1b << 16);
        }
        *(uint4*)(dhi + j * 8) = make_uint4(hw[0], hw[1], hw[2], hw[3]);
        *(uint4*)(dlo + j * 8) = make_uint4(lw[0], lw[1], lw[2], lw[3]);
    }
}

// ---------------------------------------------------------------------------
// lstm_mma: persistent 128-CTA x 256-thread mma.sync recurrence.
// ---------------------------------------------------------------------------
__global__ void __launch_bounds__(TPB, 1)
lstm_mma(const float* __restrict__ c0,
         const void*  __restrict__ pa_raw,
         const float* __restrict__ tok_embed,
         const float* __restrict__ W_ih,
         float* __restrict__ out)
{
    extern __shared__ unsigned char smem[];
    const uint32_t sb = smem_to_u32(smem);
    const int tid  = threadIdx.x;
    const int wid  = tid >> 5;
    const int lane = tid & 31;
    const int g    = blockIdx.x;
    const int is64 = g_is64;

    // ---- one-time W image copy into SMEM ----
    {
        const unsigned char* wsrc = g_wimg + (size_t)g * 132096;
        for (int i = tid; i < 8256; i += TPB) {
            CP_ASYNC16(sb + OFF_WHI + i * 16, wsrc + (size_t)i * 16);
        }
        CP_COMMIT();
        CP_WAIT0();
        __syncthreads();
    }

    // ---- epilogue identity: unit-fastest (coalesced epilogue streams) ----
    // thread -> (u_e = tid&7, bq = tid>>3); handles b = bq and b = bq+32
    const int u_e = tid & 7;
    const int bq  = tid >> 3;          // 0..31
    const int kg  = g * 8 + u_e;
    float cst0 = c0[(size_t)bq * Hh + kg];
    float cst1 = c0[(size_t)(bq + 32) * Hh + kg];
    float hst0 = 0.f;
    float hst1 = 0.f;

    // ---- GEMM identity: 8 warps = mi(2) x nj(4) ----
    const int mi = wid >> 2;
    const int nj = wid & 3;
    const uint32_t aoff = (uint32_t)((mi * 16 + (lane & 15)) * W_STRIDE
                                     + ((lane & 16) ? 16 : 0));
    const uint32_t boff = (uint32_t)((nj * 16 + (lane & 15)) * H_STRIDE
                                     + ((lane & 16) ? 16 : 0));

    // staging identity: row = tid>>2 (0..63), seg = tid&3 (32 kk each)
    const int sg_row = tid >> 2;
    const int sg_seg = tid & 3;

    float* smemD = (float*)(smem + OFF_HB0);   // 32 x 65 fp32 overlay

#pragma unroll 1
    for (int l = 0; l < Ll; l++) {
        const unsigned short* hsrc = &g_h16[l & 1][0];

        // prologue: issue chunk 0 into HB0
        {
            const unsigned short* srcH = hsrc + sg_row * 1024 + sg_seg * 32;
            const uint32_t dstH = sb + OFF_HB0 + sg_row * H_STRIDE + sg_seg * 64;
#pragma unroll
            for (int i = 0; i < 4; i++) {
                CP_ASYNC16(dstH + i * 16, srcH + i * 8);
                CP_ASYNC16(dstH + HB_LO + i * 16, srcH + 65536 + i * 8);
            }
            CP_COMMIT();
        }

        float acc[8];
#pragma unroll
        for (int i = 0; i < 8; i++) acc[i] = 0.f;

#pragma unroll 1
        for (int c = 0; c < 8; c++) {
            CP_WAIT0();
            __syncthreads();
            if (c < 7) {
                const unsigned short* srcH = hsrc + sg_row * 1024 + (c + 1) * 128 + sg_seg * 32;
                const uint32_t hb = (c & 1) ? OFF_HB0 : OFF_HB1;
                const uint32_t dstH = sb + hb + sg_row * H_STRIDE + sg_seg * 64;
#pragma unroll
                for (int i = 0; i < 4; i++) {
                    CP_ASYNC16(dstH + i * 16, srcH + i * 8);
                    CP_ASYNC16(dstH + HB_LO + i * 16, srcH + 65536 + i * 8);
                }
                CP_COMMIT();
            }

            const uint32_t hb   = (c & 1) ? OFF_HB1 : OFF_HB0;
            const uint32_t bHi  = sb + hb + boff;
            const uint32_t bLo  = bHi + HB_LO;
            const uint32_t aHiB = sb + OFF_WHI + aoff + c * 256;
            const uint32_t aLoB = aHiB + 66048;

#pragma unroll
            for (int ks = 0; ks < 8; ks++) {
                uint32_t ah0, ah1, ah2, ah3;
                uint32_t al0, al1, al2, al3;
                uint32_t bh0, bh1, bh2, bh3;
                uint32_t bl0, bl1, bl2, bl3;
                ldsm4(ah0, ah1, ah2, ah3, aHiB + ks * 32);
                ldsm4(bh0, bh1, bh2, bh3, bHi + ks * 32);
                ldsm4(al0, al1, al2, al3, aLoB + ks * 32);
                ldsm4(bl0, bl1, bl2, bl3, bLo + ks * 32);
                mma_bf16(acc[0], acc[1], acc[2], acc[3], ah0, ah1, ah2, ah3, bh0, bh2);
                mma_bf16(acc[4], acc[5], acc[6], acc[7], ah0, ah1, ah2, ah3, bh1, bh3);
                mma_bf16(acc[0], acc[1], acc[2], acc[3], ah0, ah1, ah2, ah3, bl0, bl2);
                mma_bf16(acc[4], acc[5], acc[6], acc[7], ah0, ah1, ah2, ah3, bl1, bl3);
                mma_bf16(acc[0], acc[1], acc[2], acc[3], al0, al1, al2, al3, bh0, bh2);
                mma_bf16(acc[4], acc[5], acc[6], acc[7], al0, al1, al2, al3, bh1, bh3);
            }
        }
        __syncthreads();   // computes done; HB0 free for D overlay

        // ---- write D fragments to smemD [32 rows][65] ----
        {
            const int lr = lane >> 2;
            const int lc = (lane & 3) * 2;
            const int row0 = mi * 16 + lr;
#pragma unroll
            for (int s = 0; s < 2; s++) {
                const int col = nj * 16 + s * 8 + lc;
                smemD[row0 * 65 + col]           = acc[s * 4 + 0];
                smemD[row0 * 65 + col + 1]       = acc[s * 4 + 1];
                smemD[(row0 + 8) * 65 + col]     = acc[s * 4 + 2];
                smemD[(row0 + 8) * 65 + col + 1] = acc[s * 4 + 3];
            }
        }
        __syncthreads();

        // ---- epilogue: 2 (b, u) pairs per thread (unit-fastest) ----
        {
            unsigned short* hdst = &g_h16[(l + 1) & 1][0];
#pragma unroll
            for (int e = 0; e < 2; e++) {
                const int b = bq + e * 32;
                const size_t pidx = ((size_t)l * Bz + b) * 3;
                long long ridx;
                long long tidx;
                if (is64) {
                    const long long* pp = (const long long*)pa_raw;
                    ridx = pp[pidx];
                    tidx = pp[pidx + 1];
                } else {
                    const int* pp = (const int*)pa_raw;
                    ridx = (long long)pp[pidx];
                    tidx = (long long)pp[pidx + 1];
                }
                float gv[4];
#pragma unroll
                for (int gt = 0; gt < 4; gt++) {
                    float pre = smemD[(gt * 8 + u_e) * 65 + b];
                    const int gidx = gt * 1024 + kg;
                    float xgv = g_xp[(size_t)b * G4 + gidx];
                    if (ridx >= 0 && ridx < 256) {
                        xgv += g_rp[(size_t)ridx * G4 + gidx];
                    }
                    if (tidx >= 0 && tidx < 256) {
                        xgv += g_tp[(size_t)tidx * G4 + gidx];
                    } else if (tidx >= 256 && tidx < 32000) {
                        const float* te = tok_embed + (size_t)tidx * KDIM;
                        const float* wa = W_ih + (size_t)gidx * 1024 + 512;
                        float d = 0.f;
                        for (int a = 0; a < KDIM; a++) {
                            d = fmaf(te[a], wa[a], d);
                        }
                        xgv += d;
                    }
                    gv[gt] = pre + xgv;
                }
                const float cprev = e ? cst1 : cst0;
                const float c1 = sigf(gv[1]) * cprev + sigf(gv[0]) * tanhf(gv[2]);
                const float h1 = sigf(gv[3]) * tanhf(c1);
                if (e) { cst1 = c1; hst1 = h1; }
                else   { cst0 = c1; hst0 = h1; }
                out[((size_t)l * Bz + b) * Hh + kg] = h1;

                unsigned short hh = bfbits(h1);
                unsigned short hl = bfbits(h1 - bf2f(hh));
                hdst[b * 1024 + kg]         = hh;
                hdst[65536 + b * 1024 + kg] = hl;
            }
        }

        // ---- device-wide barrier: 8 split counters, 16 arrivals each ----
        __threadfence();
        __syncthreads();
        if (tid == 0) {
            atomicAdd(&g_ctr8[(g & 7) * 32], 1u);
        }
        if (tid < 8) {
            const unsigned tgt = (unsigned)(l + 1) * 16u;
            while (*(volatile unsigned int*)&g_ctr8[tid * 32] < tgt) {
                __nanosleep(32);
            }
        }
        __syncthreads();
    }

    // ---- final h_n, c_n ----
    {
        const size_t base_hn = (size_t)Ll * Bz * Hh;
        const size_t base_cn = base_hn + (size_t)Bz * Hh;
        out[base_hn + (size_t)bq * Hh + kg]        = hst0;
        out[base_hn + (size_t)(bq + 32) * Hh + kg] = hst1;
        out[base_cn + (size_t)bq * Hh + kg]        = cst0;
        out[base_cn + (size_t)(bq + 32) * Hh + kg] = cst1;
    }
}

// ---------------------------------------------------------------------------
extern "C" void kernel_launch(void* const* d_in, const int* in_sizes, int n_in,
                              void* d_out, int out_size)
{
    const float* x    = (const float*)d_in[0];
    const void*  pa   = (const void*)d_in[1];
    // d_in[2] = mask (unused by the reference computation)
    const float* h0   = (const float*)d_in[3];
    const float* c0   = (const float*)d_in[4];
    const float* rule = (const float*)d_in[5];
    const float* toke = (const float*)d_in[6];
    const float* Wih  = (const float*)d_in[7];
    const float* Whh  = (const float*)d_in[8];
    const float* bih  = (const float*)d_in[9];
    const float* bhh  = (const float*)d_in[10];
    float* out = (float*)d_out;

    fused_proj<<<dim3(64, 4, 3), 256>>>(rule, toke, x, Wih, bih, bhh,
                                        (const int*)pa);
    prep_w<<<512, 256>>>(Whh);
    prep_h0<<<8, 256>>>(h0);

    cudaFuncSetAttribute(lstm_mma,
                         cudaFuncAttributeMaxDynamicSharedMemorySize,
                         SMEM_BYTES);
    lstm_mma<<<NCTA, TPB, SMEM_BYTES>>>(c0, pa, toke, Wih, out);
}

// round 12
// speedup vs baseline: 1.8708x; 1.2883x over previous
#include <cuda_runtime.h>
#include <cuda_bf16.h>
#include <math.h>
#include <stdint.h>

// ---------------------------------------------------------------------------
// LSTMDecoder via mma.sync bf16 (tcgen05 unavailable: harness targets
// compute_103 without the 'a' suffix).
//
// lstm_mma: 128 persistent CTAs x 512 threads. Per CTA: 8 hidden units
// (32 gate rows x 64 batch). W_hh slice resident in SMEM (132KB) all steps.
// Per step: 8 K-chunks of h streamed via cp.async double buffer; 16 warps =
// kw(2) x mi(2) x nj(4); 3-pass hi/lo bf16 m16n8k16, fp32 regs; cross-kw
// reduce in SMEM. R12 = R11 (split-counter barrier + unit-fastest epilogue,
// gathers in epilogue) + the 4-warps/SMSP GEMM split as the single new
// structural variable.
// ---------------------------------------------------------------------------

#define Bz    64
#define Hh    1024
#define Ll    128
#define G4    4096
#define KDIM  512
#define NCTA  128
#define TPB   512

__device__ float g_rp[256 * 4096];
__device__ float g_tp[256 * 4096];
__device__ float g_xp[64 * 4096];
__device__ __align__(16) unsigned char g_wimg[128u * 132096u];
__device__ __align__(16) unsigned short g_h16[2][131072];
__device__ unsigned int g_ctr8[256];   // 8 counters at stride 32 (128B apart)
__device__ int          g_is64;

// ---- smem layout (bytes, dynamic) ----
#define OFF_WHI 0
#define OFF_WLO 66048
#define OFF_HB0 132096
#define OFF_HB1 166912
#define SMEM_BYTES 201728
#define W_STRIDE 2064       // 1024 bf16 * 2B + 16 pad
#define H_STRIDE 272        // 128 bf16 * 2B + 16 pad
#define HB_LO    17408      // 64 rows * 272

// ---- helpers ---------------------------------------------------------------
__device__ __forceinline__ uint32_t smem_to_u32(const void* smem_ptr) {
    uint32_t addr;
    asm("{ .reg .u64 tmp; cvta.to.shared.u64 tmp, %1; cvt.u32.u64 %0, tmp; }"
        : "=r"(addr) : "l"(smem_ptr));
    return addr;
}

#define CP_ASYNC16(dst, src) \
    asm volatile("cp.async.cg.shared.global [%0], [%1], 16;" \
                 :: "r"((uint32_t)(dst)), "l"(src) : "memory")
#define CP_COMMIT() \
    asm volatile("cp.async.commit_group;" ::: "memory")
#define CP_WAIT0() \
    asm volatile("cp.async.wait_group 0;" ::: "memory")

__device__ __forceinline__ void ldsm4(uint32_t& r0, uint32_t& r1,
                                      uint32_t& r2, uint32_t& r3,
                                      uint32_t addr) {
    asm volatile(
        "ldmatrix.sync.aligned.m8n8.x4.shared.b16 {%0, %1, %2, %3}, [%4];"
        : "=r"(r0), "=r"(r1), "=r"(r2), "=r"(r3)
        : "r"(addr));
}

__device__ __forceinline__ void mma_bf16(float& d0, float& d1, float& d2, float& d3,
                                         uint32_t a0, uint32_t a1, uint32_t a2, uint32_t a3,
                                         uint32_t b0, uint32_t b1) {
    asm volatile(
        "mma.sync.aligned.m16n8k16.row.col.f32.bf16.bf16.f32 "
        "{%0, %1, %2, %3}, {%4, %5, %6, %7}, {%8, %9}, {%0, %1, %2, %3};"
        : "+f"(d0), "+f"(d1), "+f"(d2), "+f"(d3)
        : "r"(a0), "r"(a1), "r"(a2), "r"(a3), "r"(b0), "r"(b1));
}

__device__ __forceinline__ unsigned short bfbits(float v) {
    __nv_bfloat16 t = __float2bfloat16(v);
    return *(unsigned short*)&t;
}
__device__ __forceinline__ float bf2f(unsigned short b) {
    __nv_bfloat16 t = *(__nv_bfloat16*)&b;
    return __bfloat162float(t);
}
__device__ __forceinline__ float sigf(float x) {
    return 1.0f / (1.0f + __expf(-x));
}

// ---------------------------------------------------------------------------
// fused_proj: tables + counter reset + pa dtype sniff. grid (64,4,3), blk 256.
// ---------------------------------------------------------------------------
__global__ void fused_proj(const float* __restrict__ rule,
                           const float* __restrict__ toke,
                           const float* __restrict__ x,
                           const float* __restrict__ Wih,
                           const float* __restrict__ b1,
                           const float* __restrict__ b2,
                           const int*   __restrict__ pa32)
{
    const int z = blockIdx.z;
    const float* E;
    float* Out;
    int M;
    int colOff;
    int addBias = 0;
    if (z == 0)      { E = rule; Out = g_rp; M = 256; colOff = 512; }
    else if (z == 1) { E = toke; Out = g_tp; M = 256; colOff = 512; }
    else             { E = x;    Out = g_xp; M = 64;  colOff = 0; addBias = 1; }

    if (z == 2 && blockIdx.x == 0 && blockIdx.y == 0) {
        __shared__ int any_nz;
        if (threadIdx.x == 0) { any_nz = 0; }
        if (threadIdx.x < 8) g_ctr8[threadIdx.x * 32] = 0u;
        __syncthreads();
        if (threadIdx.x < 256 && pa32[threadIdx.x * 2 + 1] != 0)
            atomicAdd(&any_nz, 1);
        __syncthreads();
        if (threadIdx.x == 0) g_is64 = (any_nz == 0) ? 1 : 0;
    }
    if (blockIdx.y * 64 >= M) return;

    __shared__ float Es[64][17];
    __shared__ float Ws[64][17];

    const int i0 = blockIdx.y * 64;
    const int j0 = blockIdx.x * 64;
    const int t  = threadIdx.x;
    const int ty = t >> 4;
    const int tx = t & 15;

    float acc[4][4];
#pragma unroll
    for (int i = 0; i < 4; i++)
#pragma unroll
        for (int j = 0; j < 4; j++) acc[i][j] = 0.f;

    const int ii = t >> 2;
    const int a4 = (t & 3) * 4;

    for (int a0 = 0; a0 < KDIM; a0 += 16) {
        float4 ev = make_float4(0.f, 0.f, 0.f, 0.f);
        if (i0 + ii < M)
            ev = *(const float4*)(E + (size_t)(i0 + ii) * KDIM + a0 + a4);
        Es[ii][a4 + 0] = ev.x;
        Es[ii][a4 + 1] = ev.y;
        Es[ii][a4 + 2] = ev.z;
        Es[ii][a4 + 3] = ev.w;

        float4 wv = *(const float4*)(Wih + (size_t)(j0 + ii) * 1024 + colOff + a0 + a4);
        Ws[ii][a4 + 0] = wv.x;
        Ws[ii][a4 + 1] = wv.y;
        Ws[ii][a4 + 2] = wv.z;
        Ws[ii][a4 + 3] = wv.w;
        __syncthreads();

#pragma unroll
        for (int aa = 0; aa < 16; aa++) {
            float av[4];
            float bv[4];
#pragma unroll
            for (int r2 = 0; r2 < 4; r2++) av[r2] = Es[ty * 4 + r2][aa];
#pragma unroll
            for (int r2 = 0; r2 < 4; r2++) bv[r2] = Ws[tx * 4 + r2][aa];
#pragma unroll
            for (int i = 0; i < 4; i++)
#pragma unroll
                for (int j = 0; j < 4; j++) acc[i][j] = fmaf(av[i], bv[j], acc[i][j]);
        }
        __syncthreads();
    }

#pragma unroll
    for (int i = 0; i < 4; i++) {
        int gi = i0 + ty * 4 + i;
        if (gi >= M) continue;
#pragma unroll
        for (int j = 0; j < 4; j++) {
            int gj = j0 + tx * 4 + j;
            float v = acc[i][j];
            if (addBias) v += b1[gj] + b2[gj];
            Out[(size_t)gi * G4 + gj] = v;
        }
    }
}

// ---------------------------------------------------------------------------
// prep_w: bake W_hh into per-CTA bf16 hi/lo images (SMEM layout, stride 2064).
// ---------------------------------------------------------------------------
__global__ void prep_w(const float* __restrict__ Whh)
{
    const int id   = blockIdx.x * 256 + threadIdx.x;
    const int g    = id >> 10;
    const int r    = (id >> 5) & 31;
    const int kseg = id & 31;
    const int k0   = kseg * 32;
    const int gate = r >> 3;
    const int u    = r & 7;

    const float* src = Whh + (size_t)(gate * 1024 + g * 8 + u) * 1024 + k0;
    unsigned char* dhi = g_wimg + (size_t)g * 132096 + r * W_STRIDE + k0 * 2;
    unsigned char* dlo = dhi + 66048;

#pragma unroll
    for (int j = 0; j < 4; j++) {
        float4 va = *(const float4*)(src + j * 8);
        float4 vb = *(const float4*)(src + j * 8 + 4);
        float v[8];
        v[0] = va.x; v[1] = va.y; v[2] = va.z; v[3] = va.w;
        v[4] = vb.x; v[5] = vb.y; v[6] = vb.z; v[7] = vb.w;
        unsigned int hw[4];
        unsigned int lw[4];
#pragma unroll
        for (int q = 0; q < 4; q++) {
            unsigned short h0 = bfbits(v[2 * q]);
            unsigned short l0 = bfbits(v[2 * q] - bf2f(h0));
            unsigned short h1 = bfbits(v[2 * q + 1]);
            unsigned short l1 = bfbits(v[2 * q + 1] - bf2f(h1));
            hw[q] = (unsigned)h0 | ((unsigned)h1 << 16);
            lw[q] = (unsigned)l0 | ((unsigned)l1 << 16);
        }
        *(uint4*)(dhi + j * 16) = make_uint4(hw[0], hw[1], hw[2], hw[3]);
        *(uint4*)(dlo + j * 16) = make_uint4(lw[0], lw[1], lw[2], lw[3]);
    }
}

// ---------------------------------------------------------------------------
// prep_h0: bake initial h into g_h16 parity 0.
// ---------------------------------------------------------------------------
__global__ void prep_h0(const float* __restrict__ h0)
{
    const int id = blockIdx.x * 256 + threadIdx.x;
    if (id >= 2048) return;
    const int b    = id >> 5;
    const int kseg = id & 31;
    const int k0   = kseg * 32;

    const float* src = h0 + (size_t)b * 1024 + k0;
    unsigned short* dhi = &g_h16[0][b * 1024 + k0];
    unsigned short* dlo = dhi + 65536;

#pragma unroll
    for (int j = 0; j < 4; j++) {
        float4 va = *(const float4*)(src + j * 8);
        float4 vb = *(const float4*)(src + j * 8 + 4);
        float v[8];
        v[0] = va.x; v[1] = va.y; v[2] = va.z; v[3] = va.w;
        v[4] = vb.x; v[5] = vb.y; v[6] = vb.z; v[7] = vb.w;
        unsigned int hw[4];
        unsigned int lw[4];
#pragma unroll
        for (int q = 0; q < 4; q++) {
            unsigned short h0b = bfbits(v[2 * q]);
            unsigned short l0b = bfbits(v[2 * q] - bf2f(h0b));
            unsigned short h1b = bfbits(v[2 * q + 1]);
            unsigned short l1b = bfbits(v[2 * q + 1] - bf2f(h1b));
            hw[q] = (unsigned)h0b | ((unsigned)h1b << 16);
            lw[q] = (unsigned)l0b | ((unsigned)l1b << 16);
        }
        *(uint4*)(dhi + j * 8) = make_uint4(hw[0], hw[1], hw[2], hw[3]);
        *(uint4*)(dlo + j * 8) = make_uint4(lw[0], lw[1], lw[2], lw[3]);
    }
}

// ---------------------------------------------------------------------------
// lstm_mma: persistent 128-CTA x 512-thread mma.sync recurrence.
// ---------------------------------------------------------------------------
__global__ void __launch_bounds__(TPB, 1)
lstm_mma(const float* __restrict__ c0,
         const void*  __restrict__ pa_raw,
         const float* __restrict__ tok_embed,
         const float* __restrict__ W_ih,
         float* __restrict__ out)
{
    extern __shared__ unsigned char smem[];
    const uint32_t sb = smem_to_u32(smem);
    const int tid  = threadIdx.x;
    const int wid  = tid >> 5;
    const int lane = tid & 31;
    const int g    = blockIdx.x;
    const int is64 = g_is64;

    // ---- one-time W image copy into SMEM ----
    {
        const unsigned char* wsrc = g_wimg + (size_t)g * 132096;
        for (int i = tid; i < 8256; i += TPB) {
            CP_ASYNC16(sb + OFF_WHI + i * 16, wsrc + (size_t)i * 16);
        }
        CP_COMMIT();
        CP_WAIT0();
        __syncthreads();
    }

    // ---- epilogue identity: 1 (b, u) pair per thread, unit-fastest ----
    const int u_e = tid & 7;
    const int b_e = tid >> 3;          // 0..63
    const int kg  = g * 8 + u_e;
    float cst = c0[(size_t)b_e * Hh + kg];
    float hst = 0.f;

    // ---- GEMM identity: 16 warps = kw(2) x mi(2) x nj(4) ----
    const int kw = wid >> 3;
    const int mi = (wid >> 2) & 1;
    const int nj = wid & 3;
    const uint32_t aoff = (uint32_t)((mi * 16 + (lane & 15)) * W_STRIDE
                                     + ((lane & 16) ? 16 : 0));
    const uint32_t boff = (uint32_t)((nj * 16 + (lane & 15)) * H_STRIDE
                                     + ((lane & 16) ? 16 : 0));

    // staging identity: row = tid>>3 (0..63), seg = tid&7 (16 kk each)
    const int sg_row = tid >> 3;
    const int sg_seg = tid & 7;

    float* smemD = (float*)(smem + OFF_HB0);   // [kw][32][65] fp32 overlay

#pragma unroll 1
    for (int l = 0; l < Ll; l++) {
        const unsigned short* hsrc = &g_h16[l & 1][0];

        // prologue: issue chunk 0 into HB0
        {
            const unsigned short* srcH = hsrc + sg_row * 1024 + sg_seg * 16;
            const uint32_t dstH = sb + OFF_HB0 + sg_row * H_STRIDE + sg_seg * 32;
            CP_ASYNC16(dstH,              srcH);
            CP_ASYNC16(dstH + 16,         srcH + 8);
            CP_ASYNC16(dstH + HB_LO,      srcH + 65536);
            CP_ASYNC16(dstH + HB_LO + 16, srcH + 65536 + 8);
            CP_COMMIT();
        }

        float acc[8];
#pragma unroll
        for (int i = 0; i < 8; i++) acc[i] = 0.f;

#pragma unroll 1
        for (int c = 0; c < 8; c++) {
            CP_WAIT0();
            __syncthreads();
            if (c < 7) {
                const unsigned short* srcH = hsrc + sg_row * 1024 + (c + 1) * 128 + sg_seg * 16;
                const uint32_t hb = (c & 1) ? OFF_HB0 : OFF_HB1;
                const uint32_t dstH = sb + hb + sg_row * H_STRIDE + sg_seg * 32;
                CP_ASYNC16(dstH,              srcH);
                CP_ASYNC16(dstH + 16,         srcH + 8);
                CP_ASYNC16(dstH + HB_LO,      srcH + 65536);
                CP_ASYNC16(dstH + HB_LO + 16, srcH + 65536 + 8);
                CP_COMMIT();
            }

            const uint32_t hb   = (c & 1) ? OFF_HB1 : OFF_HB0;
            const uint32_t bHi  = sb + hb + boff + kw * 128;
            const uint32_t bLo  = bHi + HB_LO;
            const uint32_t aHiB = sb + OFF_WHI + aoff + c * 256 + kw * 128;
            const uint32_t aLoB = aHiB + 66048;

#pragma unroll
            for (int ks = 0; ks < 4; ks++) {
                uint32_t ah0, ah1, ah2, ah3;
                uint32_t al0, al1, al2, al3;
                uint32_t bh0, bh1, bh2, bh3;
                uint32_t bl0, bl1, bl2, bl3;
                ldsm4(ah0, ah1, ah2, ah3, aHiB + ks * 32);
                ldsm4(bh0, bh1, bh2, bh3, bHi + ks * 32);
                ldsm4(al0, al1, al2, al3, aLoB + ks * 32);
                ldsm4(bl0, bl1, bl2, bl3, bLo + ks * 32);
                mma_bf16(acc[0], acc[1], acc[2], acc[3], ah0, ah1, ah2, ah3, bh0, bh2);
                mma_bf16(acc[4], acc[5], acc[6], acc[7], ah0, ah1, ah2, ah3, bh1, bh3);
                mma_bf16(acc[0], acc[1], acc[2], acc[3], ah0, ah1, ah2, ah3, bl0, bl2);
                mma_bf16(acc[4], acc[5], acc[6], acc[7], ah0, ah1, ah2, ah3, bl1, bl3);
                mma_bf16(acc[0], acc[1], acc[2], acc[3], al0, al1, al2, al3, bh0, bh2);
                mma_bf16(acc[4], acc[5], acc[6], acc[7], al0, al1, al2, al3, bh1, bh3);
            }
        }
        __syncthreads();   // computes done; HB0/HB1 free for D overlay

        // ---- write D fragments to smemD[kw][32][65] ----
        {
            const int lr = lane >> 2;
            const int lc = (lane & 3) * 2;
            const int row0 = mi * 16 + lr;
            float* dk = smemD + kw * 2080;
#pragma unroll
            for (int s = 0; s < 2; s++) {
                const int col = nj * 16 + s * 8 + lc;
                dk[row0 * 65 + col]           = acc[s * 4 + 0];
                dk[row0 * 65 + col + 1]       = acc[s * 4 + 1];
                dk[(row0 + 8) * 65 + col]     = acc[s * 4 + 2];
                dk[(row0 + 8) * 65 + col + 1] = acc[s * 4 + 3];
            }
        }
        __syncthreads();

        // ---- epilogue: 1 (b, u) pair per thread (unit-fastest) ----
        {
            unsigned short* hdst = &g_h16[(l + 1) & 1][0];
            const size_t pidx = ((size_t)l * Bz + b_e) * 3;
            long long ridx;
            long long tidx;
            if (is64) {
                const long long* pp = (const long long*)pa_raw;
                ridx = pp[pidx];
                tidx = pp[pidx + 1];
            } else {
                const int* pp = (const int*)pa_raw;
                ridx = (long long)pp[pidx];
                tidx = (long long)pp[pidx + 1];
            }
            float gv[4];
#pragma unroll
            for (int gt = 0; gt < 4; gt++) {
                const int row = gt * 8 + u_e;
                float pre = smemD[row * 65 + b_e] + smemD[2080 + row * 65 + b_e];
                const int gidx = gt * 1024 + kg;
                float xgv = g_xp[(size_t)b_e * G4 + gidx];
                if (ridx >= 0 && ridx < 256) {
                    xgv += g_rp[(size_t)ridx * G4 + gidx];
                }
                if (tidx >= 0 && tidx < 256) {
                    xgv += g_tp[(size_t)tidx * G4 + gidx];
                } else if (tidx >= 256 && tidx < 32000) {
                    const float* te = tok_embed + (size_t)tidx * KDIM;
                    const float* wa = W_ih + (size_t)gidx * 1024 + 512;
                    float d = 0.f;
                    for (int a = 0; a < KDIM; a++) {
                        d = fmaf(te[a], wa[a], d);
                    }
                    xgv += d;
                }
                gv[gt] = pre + xgv;
            }
            const float c1 = sigf(gv[1]) * cst + sigf(gv[0]) * tanhf(gv[2]);
            const float h1 = sigf(gv[3]) * tanhf(c1);
            cst = c1;
            hst = h1;
            out[((size_t)l * Bz + b_e) * Hh + kg] = h1;

            unsigned short hh = bfbits(h1);
            unsigned short hl = bfbits(h1 - bf2f(hh));
            hdst[b_e * 1024 + kg]         = hh;
            hdst[65536 + b_e * 1024 + kg] = hl;
        }

        // ---- device-wide barrier: 8 split counters, 16 arrivals each ----
        __threadfence();
        __syncthreads();
        if (tid == 0) {
            atomicAdd(&g_ctr8[(g & 7) * 32], 1u);
        }
        if (tid < 8) {
            const unsigned tgt = (unsigned)(l + 1) * 16u;
            while (*(volatile unsigned int*)&g_ctr8[tid * 32] < tgt) {
                __nanosleep(32);
            }
        }
        __syncthreads();
    }

    // ---- final h_n, c_n ----
    {
        const size_t base_hn = (size_t)Ll * Bz * Hh;
        const size_t base_cn = base_hn + (size_t)Bz * Hh;
        out[base_hn + (size_t)b_e * Hh + kg] = hst;
        out[base_cn + (size_t)b_e * Hh + kg] = cst;
    }
}

// ---------------------------------------------------------------------------
extern "C" void kernel_launch(void* const* d_in, const int* in_sizes, int n_in,
                              void* d_out, int out_size)
{
    const float* x    = (const float*)d_in[0];
    const void*  pa   = (const void*)d_in[1];
    // d_in[2] = mask (unused by the reference computation)
    const float* h0   = (const float*)d_in[3];
    const float* c0   = (const float*)d_in[4];
    const float* rule = (const float*)d_in[5];
    const float* toke = (const float*)d_in[6];
    const float* Wih  = (const float*)d_in[7];
    const float* Whh  = (const float*)d_in[8];
    const float* bih  = (const float*)d_in[9];
    const float* bhh  = (const float*)d_in[10];
    float* out = (float*)d_out;

    fused_proj<<<dim3(64, 4, 3), 256>>>(rule, toke, x, Wih, bih, bhh,
                                        (const int*)pa);
    prep_w<<<512, 256>>>(Whh);
    prep_h0<<<8, 256>>>(h0);

    cudaFuncSetAttribute(lstm_mma,
                         cudaFuncAttributeMaxDynamicSharedMemorySize,
                         SMEM_BYTES);
    lstm_mma<<<NCTA, TPB, SMEM_BYTES>>>(c0, pa, toke, Wih, out);
}

// round 13
// speedup vs baseline: 1.8927x; 1.0117x over previous
#include <cuda_runtime.h>
#include <cuda_bf16.h>
#include <math.h>
#include <stdint.h>

// ---------------------------------------------------------------------------
// LSTMDecoder via mma.sync bf16 (tcgen05 unavailable: harness targets
// compute_103 without the 'a' suffix).
//
// lstm_mma: 128 persistent CTAs x 512 threads. Per CTA: 8 hidden units
// (32 gate rows x 64 batch). W_hh slice resident in SMEM (132KB) all steps.
// Per step: 8 K-chunks of h streamed via cp.async double buffer; 16 warps =
// kw(4) x mi(2) x nj(2) [R13 retile: 6 LDSM per 12 MMAs, 4 indep acc chains];
// 3-pass hi/lo bf16 m16n8k16, fp32 regs; 4-way cross-kw reduce in SMEM;
// unit-fastest epilogue with gathers; split-counter barrier.
// ---------------------------------------------------------------------------

#define Bz    64
#define Hh    1024
#define Ll    128
#define G4    4096
#define KDIM  512
#define NCTA  128
#define TPB   512

__device__ float g_rp[256 * 4096];
__device__ float g_tp[256 * 4096];
__device__ float g_xp[64 * 4096];
__device__ __align__(16) unsigned char g_wimg[128u * 132096u];
__device__ __align__(16) unsigned short g_h16[2][131072];
__device__ unsigned int g_ctr8[256];   // 8 counters at stride 32 (128B apart)
__device__ int          g_is64;

// ---- smem layout (bytes, dynamic) ----
#define OFF_WHI 0
#define OFF_WLO 66048
#define OFF_HB0 132096
#define OFF_HB1 166912
#define SMEM_BYTES 201728
#define W_STRIDE 2064       // 1024 bf16 * 2B + 16 pad
#define H_STRIDE 272        // 128 bf16 * 2B + 16 pad
#define HB_LO    17408      // 64 rows * 272

// ---- helpers ---------------------------------------------------------------
__device__ __forceinline__ uint32_t smem_to_u32(const void* smem_ptr) {
    uint32_t addr;
    asm("{ .reg .u64 tmp; cvta.to.shared.u64 tmp, %1; cvt.u32.u64 %0, tmp; }"
        : "=r"(addr) : "l"(smem_ptr));
    return addr;
}

#define CP_ASYNC16(dst, src) \
    asm volatile("cp.async.cg.shared.global [%0], [%1], 16;" \
                 :: "r"((uint32_t)(dst)), "l"(src) : "memory")
#define CP_COMMIT() \
    asm volatile("cp.async.commit_group;" ::: "memory")
#define CP_WAIT0() \
    asm volatile("cp.async.wait_group 0;" ::: "memory")

__device__ __forceinline__ void ldsm4(uint32_t& r0, uint32_t& r1,
                                      uint32_t& r2, uint32_t& r3,
                                      uint32_t addr) {
    asm volatile(
        "ldmatrix.sync.aligned.m8n8.x4.shared.b16 {%0, %1, %2, %3}, [%4];"
        : "=r"(r0), "=r"(r1), "=r"(r2), "=r"(r3)
        : "r"(addr));
}

__device__ __forceinline__ void mma_bf16(float& d0, float& d1, float& d2, float& d3,
                                         uint32_t a0, uint32_t a1, uint32_t a2, uint32_t a3,
                                         uint32_t b0, uint32_t b1) {
    asm volatile(
        "mma.sync.aligned.m16n8k16.row.col.f32.bf16.bf16.f32 "
        "{%0, %1, %2, %3}, {%4, %5, %6, %7}, {%8, %9}, {%0, %1, %2, %3};"
        : "+f"(d0), "+f"(d1), "+f"(d2), "+f"(d3)
        : "r"(a0), "r"(a1), "r"(a2), "r"(a3), "r"(b0), "r"(b1));
}

__device__ __forceinline__ unsigned short bfbits(float v) {
    __nv_bfloat16 t = __float2bfloat16(v);
    return *(unsigned short*)&t;
}
__device__ __forceinline__ float bf2f(unsigned short b) {
    __nv_bfloat16 t = *(__nv_bfloat16*)&b;
    return __bfloat162float(t);
}
__device__ __forceinline__ float sigf(float x) {
    return 1.0f / (1.0f + __expf(-x));
}

// ---------------------------------------------------------------------------
// fused_proj: tables + counter reset + pa dtype sniff. grid (64,4,3), blk 256.
// ---------------------------------------------------------------------------
__global__ void fused_proj(const float* __restrict__ rule,
                           const float* __restrict__ toke,
                           const float* __restrict__ x,
                           const float* __restrict__ Wih,
                           const float* __restrict__ b1,
                           const float* __restrict__ b2,
                           const int*   __restrict__ pa32)
{
    const int z = blockIdx.z;
    const float* E;
    float* Out;
    int M;
    int colOff;
    int addBias = 0;
    if (z == 0)      { E = rule; Out = g_rp; M = 256; colOff = 512; }
    else if (z == 1) { E = toke; Out = g_tp; M = 256; colOff = 512; }
    else             { E = x;    Out = g_xp; M = 64;  colOff = 0; addBias = 1; }

    if (z == 2 && blockIdx.x == 0 && blockIdx.y == 0) {
        __shared__ int any_nz;
        if (threadIdx.x == 0) { any_nz = 0; }
        if (threadIdx.x < 8) g_ctr8[threadIdx.x * 32] = 0u;
        __syncthreads();
        if (threadIdx.x < 256 && pa32[threadIdx.x * 2 + 1] != 0)
            atomicAdd(&any_nz, 1);
        __syncthreads();
        if (threadIdx.x == 0) g_is64 = (any_nz == 0) ? 1 : 0;
    }
    if (blockIdx.y * 64 >= M) return;

    __shared__ float Es[64][17];
    __shared__ float Ws[64][17];

    const int i0 = blockIdx.y * 64;
    const int j0 = blockIdx.x * 64;
    const int t  = threadIdx.x;
    const int ty = t >> 4;
    const int tx = t & 15;

    float acc[4][4];
#pragma unroll
    for (int i = 0; i < 4; i++)
#pragma unroll
        for (int j = 0; j < 4; j++) acc[i][j] = 0.f;

    const int ii = t >> 2;
    const int a4 = (t & 3) * 4;

    for (int a0 = 0; a0 < KDIM; a0 += 16) {
        float4 ev = make_float4(0.f, 0.f, 0.f, 0.f);
        if (i0 + ii < M)
            ev = *(const float4*)(E + (size_t)(i0 + ii) * KDIM + a0 + a4);
        Es[ii][a4 + 0] = ev.x;
        Es[ii][a4 + 1] = ev.y;
        Es[ii][a4 + 2] = ev.z;
        Es[ii][a4 + 3] = ev.w;

        float4 wv = *(const float4*)(Wih + (size_t)(j0 + ii) * 1024 + colOff + a0 + a4);
        Ws[ii][a4 + 0] = wv.x;
        Ws[ii][a4 + 1] = wv.y;
        Ws[ii][a4 + 2] = wv.z;
        Ws[ii][a4 + 3] = wv.w;
        __syncthreads();

#pragma unroll
        for (int aa = 0; aa < 16; aa++) {
            float av[4];
            float bv[4];
#pragma unroll
            for (int r2 = 0; r2 < 4; r2++) av[r2] = Es[ty * 4 + r2][aa];
#pragma unroll
            for (int r2 = 0; r2 < 4; r2++) bv[r2] = Ws[tx * 4 + r2][aa];
#pragma unroll
            for (int i = 0; i < 4; i++)
#pragma unroll
                for (int j = 0; j < 4; j++) acc[i][j] = fmaf(av[i], bv[j], acc[i][j]);
        }
        __syncthreads();
    }

#pragma unroll
    for (int i = 0; i < 4; i++) {
        int gi = i0 + ty * 4 + i;
        if (gi >= M) continue;
#pragma unroll
        for (int j = 0; j < 4; j++) {
            int gj = j0 + tx * 4 + j;
            float v = acc[i][j];
            if (addBias) v += b1[gj] + b2[gj];
            Out[(size_t)gi * G4 + gj] = v;
        }
    }
}

// ---------------------------------------------------------------------------
// prep_w: bake W_hh into per-CTA bf16 hi/lo images (SMEM layout, stride 2064).
// ---------------------------------------------------------------------------
__global__ void prep_w(const float* __restrict__ Whh)
{
    const int id   = blockIdx.x * 256 + threadIdx.x;
    const int g    = id >> 10;
    const int r    = (id >> 5) & 31;
    const int kseg = id & 31;
    const int k0   = kseg * 32;
    const int gate = r >> 3;
    const int u    = r & 7;

    const float* src = Whh + (size_t)(gate * 1024 + g * 8 + u) * 1024 + k0;
    unsigned char* dhi = g_wimg + (size_t)g * 132096 + r * W_STRIDE + k0 * 2;
    unsigned char* dlo = dhi + 66048;

#pragma unroll
    for (int j = 0; j < 4; j++) {
        float4 va = *(const float4*)(src + j * 8);
        float4 vb = *(const float4*)(src + j * 8 + 4);
        float v[8];
        v[0] = va.x; v[1] = va.y; v[2] = va.z; v[3] = va.w;
        v[4] = vb.x; v[5] = vb.y; v[6] = vb.z; v[7] = vb.w;
        unsigned int hw[4];
        unsigned int lw[4];
#pragma unroll
        for (int q = 0; q < 4; q++) {
            unsigned short h0 = bfbits(v[2 * q]);
            unsigned short l0 = bfbits(v[2 * q] - bf2f(h0));
            unsigned short h1 = bfbits(v[2 * q + 1]);
            unsigned short l1 = bfbits(v[2 * q + 1] - bf2f(h1));
            hw[q] = (unsigned)h0 | ((unsigned)h1 << 16);
            lw[q] = (unsigned)l0 | ((unsigned)l1 << 16);
        }
        *(uint4*)(dhi + j * 16) = make_uint4(hw[0], hw[1], hw[2], hw[3]);
        *(uint4*)(dlo + j * 16) = make_uint4(lw[0], lw[1], lw[2], lw[3]);
    }
}

// ---------------------------------------------------------------------------
// prep_h0: bake initial h into g_h16 parity 0.
// ---------------------------------------------------------------------------
__global__ void prep_h0(const float* __restrict__ h0)
{
    const int id = blockIdx.x * 256 + threadIdx.x;
    if (id >= 2048) return;
    const int b    = id >> 5;
    const int kseg = id & 31;
    const int k0   = kseg * 32;

    const float* src = h0 + (size_t)b * 1024 + k0;
    unsigned short* dhi = &g_h16[0][b * 1024 + k0];
    unsigned short* dlo = dhi + 65536;

#pragma unroll
    for (int j = 0; j < 4; j++) {
        float4 va = *(const float4*)(src + j * 8);
        float4 vb = *(const float4*)(src + j * 8 + 4);
        float v[8];
        v[0] = va.x; v[1] = va.y; v[2] = va.z; v[3] = va.w;
        v[4] = vb.x; v[5] = vb.y; v[6] = vb.z; v[7] = vb.w;
        unsigned int hw[4];
        unsigned int lw[4];
#pragma unroll
        for (int q = 0; q < 4; q++) {
            unsigned short h0b = bfbits(v[2 * q]);
            unsigned short l0b = bfbits(v[2 * q] - bf2f(h0b));
            unsigned short h1b = bfbits(v[2 * q + 1]);
            unsigned short l1b = bfbits(v[2 * q + 1] - bf2f(h1b));
            hw[q] = (unsigned)h0b | ((unsigned)h1b << 16);
            lw[q] = (unsigned)l0b | ((unsigned)l1b << 16);
        }
        *(uint4*)(dhi + j * 8) = make_uint4(hw[0], hw[1], hw[2], hw[3]);
        *(uint4*)(dlo + j * 8) = make_uint4(lw[0], lw[1], lw[2], lw[3]);
    }
}

// ---------------------------------------------------------------------------
// lstm_mma: persistent 128-CTA x 512-thread mma.sync recurrence.
// ---------------------------------------------------------------------------
__global__ void __launch_bounds__(TPB, 1)
lstm_mma(const float* __restrict__ c0,
         const void*  __restrict__ pa_raw,
         const float* __restrict__ tok_embed,
         const float* __restrict__ W_ih,
         float* __restrict__ out)
{
    extern __shared__ unsigned char smem[];
    const uint32_t sb = smem_to_u32(smem);
    const int tid  = threadIdx.x;
    const int wid  = tid >> 5;
    const int lane = tid & 31;
    const int g    = blockIdx.x;
    const int is64 = g_is64;

    // ---- one-time W image copy into SMEM ----
    {
        const unsigned char* wsrc = g_wimg + (size_t)g * 132096;
        for (int i = tid; i < 8256; i += TPB) {
            CP_ASYNC16(sb + OFF_WHI + i * 16, wsrc + (size_t)i * 16);
        }
        CP_COMMIT();
        CP_WAIT0();
        __syncthreads();
    }

    // ---- epilogue identity: 1 (b, u) pair per thread, unit-fastest ----
    const int u_e = tid & 7;
    const int b_e = tid >> 3;          // 0..63
    const int kg  = g * 8 + u_e;
    float cst = c0[(size_t)b_e * Hh + kg];
    float hst = 0.f;

    // ---- GEMM identity: 16 warps = kw(4) x mi(2) x nj(2) ----
    const int kw = wid >> 2;           // 0..3  (32 kk each within a chunk)
    const int mi = (wid >> 1) & 1;     // 0..1  (16 gate rows)
    const int nj = wid & 1;            // 0..1  (32 batches)
    const uint32_t aoff = (uint32_t)((mi * 16 + (lane & 15)) * W_STRIDE
                                     + ((lane & 16) ? 16 : 0));
    const uint32_t boff = (uint32_t)((nj * 32 + (lane & 15)) * H_STRIDE
                                     + ((lane & 16) ? 16 : 0));

    // staging identity: row = tid>>3 (0..63), seg = tid&7 (16 kk each)
    const int sg_row = tid >> 3;
    const int sg_seg = tid & 7;

    float* smemD = (float*)(smem + OFF_HB0);   // [kw 4][32][65] fp32 overlay

#pragma unroll 1
    for (int l = 0; l < Ll; l++) {
        const unsigned short* hsrc = &g_h16[l & 1][0];

        // prologue: issue chunk 0 into HB0
        {
            const unsigned short* srcH = hsrc + sg_row * 1024 + sg_seg * 16;
            const uint32_t dstH = sb + OFF_HB0 + sg_row * H_STRIDE + sg_seg * 32;
            CP_ASYNC16(dstH,              srcH);
            CP_ASYNC16(dstH + 16,         srcH + 8);
            CP_ASYNC16(dstH + HB_LO,      srcH + 65536);
            CP_ASYNC16(dstH + HB_LO + 16, srcH + 65536 + 8);
            CP_COMMIT();
        }

        float acc[16];
#pragma unroll
        for (int i = 0; i < 16; i++) acc[i] = 0.f;

#pragma unroll 1
        for (int c = 0; c < 8; c++) {
            CP_WAIT0();
            __syncthreads();
            if (c < 7) {
                const unsigned short* srcH = hsrc + sg_row * 1024 + (c + 1) * 128 + sg_seg * 16;
                const uint32_t hb = (c & 1) ? OFF_HB0 : OFF_HB1;
                const uint32_t dstH = sb + hb + sg_row * H_STRIDE + sg_seg * 32;
                CP_ASYNC16(dstH,              srcH);
                CP_ASYNC16(dstH + 16,         srcH + 8);
                CP_ASYNC16(dstH + HB_LO,      srcH + 65536);
                CP_ASYNC16(dstH + HB_LO + 16, srcH + 65536 + 8);
                CP_COMMIT();
            }

            const uint32_t hb   = (c & 1) ? OFF_HB1 : OFF_HB0;
            const uint32_t bHi  = sb + hb + boff + kw * 64;
            const uint32_t bLo  = bHi + HB_LO;
            const uint32_t aHiB = sb + OFF_WHI + aoff + c * 256 + kw * 64;
            const uint32_t aLoB = aHiB + 66048;

#pragma unroll
            for (int ks = 0; ks < 2; ks++) {
                uint32_t ah0, ah1, ah2, ah3;
                uint32_t al0, al1, al2, al3;
                uint32_t bh0, bh1, bh2, bh3, bh4, bh5, bh6, bh7;
                uint32_t bl0, bl1, bl2, bl3, bl4, bl5, bl6, bl7;
                ldsm4(ah0, ah1, ah2, ah3, aHiB + ks * 32);
                ldsm4(al0, al1, al2, al3, aLoB + ks * 32);
                ldsm4(bh0, bh1, bh2, bh3, bHi + ks * 32);
                ldsm4(bh4, bh5, bh6, bh7, bHi + 16 * H_STRIDE + ks * 32);
                ldsm4(bl0, bl1, bl2, bl3, bLo + ks * 32);
                ldsm4(bl4, bl5, bl6, bl7, bLo + 16 * H_STRIDE + ks * 32);
                // group 0: cols +0..7   {bh0,bh2}
                mma_bf16(acc[0],  acc[1],  acc[2],  acc[3],  ah0, ah1, ah2, ah3, bh0, bh2);
                mma_bf16(acc[0],  acc[1],  acc[2],  acc[3],  ah0, ah1, ah2, ah3, bl0, bl2);
                mma_bf16(acc[0],  acc[1],  acc[2],  acc[3],  al0, al1, al2, al3, bh0, bh2);
                // group 1: cols +8..15  {bh1,bh3}
                mma_bf16(acc[4],  acc[5],  acc[6],  acc[7],  ah0, ah1, ah2, ah3, bh1, bh3);
                mma_bf16(acc[4],  acc[5],  acc[6],  acc[7],  ah0, ah1, ah2, ah3, bl1, bl3);
                mma_bf16(acc[4],  acc[5],  acc[6],  acc[7],  al0, al1, al2, al3, bh1, bh3);
                // group 2: cols +16..23 {bh4,bh6}
                mma_bf16(acc[8],  acc[9],  acc[10], acc[11], ah0, ah1, ah2, ah3, bh4, bh6);
                mma_bf16(acc[8],  acc[9],  acc[10], acc[11], ah0, ah1, ah2, ah3, bl4, bl6);
                mma_bf16(acc[8],  acc[9],  acc[10], acc[11], al0, al1, al2, al3, bh4, bh6);
                // group 3: cols +24..31 {bh5,bh7}
                mma_bf16(acc[12], acc[13], acc[14], acc[15], ah0, ah1, ah2, ah3, bh5, bh7);
                mma_bf16(acc[12], acc[13], acc[14], acc[15], ah0, ah1, ah2, ah3, bl5, bl7);
                mma_bf16(acc[12], acc[13], acc[14], acc[15], al0, al1, al2, al3, bh5, bh7);
            }
        }
        __syncthreads();   // computes done; HB0/HB1 free for D overlay

        // ---- write D fragments to smemD[kw][32][65] ----
        {
            const int lr = lane >> 2;
            const int lc = (lane & 3) * 2;
            const int row0 = mi * 16 + lr;
            float* dk = smemD + kw * 2080;
#pragma unroll
            for (int s = 0; s < 4; s++) {
                const int col = nj * 32 + s * 8 + lc;
                dk[row0 * 65 + col]           = acc[s * 4 + 0];
                dk[row0 * 65 + col + 1]       = acc[s * 4 + 1];
                dk[(row0 + 8) * 65 + col]     = acc[s * 4 + 2];
                dk[(row0 + 8) * 65 + col + 1] = acc[s * 4 + 3];
            }
        }
        __syncthreads();

        // ---- epilogue: 1 (b, u) pair per thread (unit-fastest) ----
        {
            unsigned short* hdst = &g_h16[(l + 1) & 1][0];
            const size_t pidx = ((size_t)l * Bz + b_e) * 3;
            long long ridx;
            long long tidx;
            if (is64) {
                const long long* pp = (const long long*)pa_raw;
                ridx = pp[pidx];
                tidx = pp[pidx + 1];
            } else {
                const int* pp = (const int*)pa_raw;
                ridx = (long long)pp[pidx];
                tidx = (long long)pp[pidx + 1];
            }
            float gv[4];
#pragma unroll
            for (int gt = 0; gt < 4; gt++) {
                const int row = gt * 8 + u_e;
                float pre = smemD[row * 65 + b_e]
                          + smemD[2080 + row * 65 + b_e]
                          + smemD[4160 + row * 65 + b_e]
                          + smemD[6240 + row * 65 + b_e];
                const int gidx = gt * 1024 + kg;
                float xgv = g_xp[(size_t)b_e * G4 + gidx];
                if (ridx >= 0 && ridx < 256) {
                    xgv += g_rp[(size_t)ridx * G4 + gidx];
                }
                if (tidx >= 0 && tidx < 256) {
                    xgv += g_tp[(size_t)tidx * G4 + gidx];
                } else if (tidx >= 256 && tidx < 32000) {
                    const float* te = tok_embed + (size_t)tidx * KDIM;
                    const float* wa = W_ih + (size_t)gidx * 1024 + 512;
                    float d = 0.f;
                    for (int a = 0; a < KDIM; a++) {
                        d = fmaf(te[a], wa[a], d);
                    }
                    xgv += d;
                }
                gv[gt] = pre + xgv;
            }
            const float c1 = sigf(gv[1]) * cst + sigf(gv[0]) * tanhf(gv[2]);
            const float h1 = sigf(gv[3]) * tanhf(c1);
            cst = c1;
            hst = h1;
            out[((size_t)l * Bz + b_e) * Hh + kg] = h1;

            unsigned short hh = bfbits(h1);
            unsigned short hl = bfbits(h1 - bf2f(hh));
            hdst[b_e * 1024 + kg]         = hh;
            hdst[65536 + b_e * 1024 + kg] = hl;
        }

        // ---- device-wide barrier: 8 split counters, 16 arrivals each ----
        __threadfence();
        __syncthreads();
        if (tid == 0) {
            atomicAdd(&g_ctr8[(g & 7) * 32], 1u);
        }
        if (tid < 8) {
            const unsigned tgt = (unsigned)(l + 1) * 16u;
            while (*(volatile unsigned int*)&g_ctr8[tid * 32] < tgt) {
                __nanosleep(32);
            }
        }
        __syncthreads();
    }

    // ---- final h_n, c_n ----
    {
        const size_t base_hn = (size_t)Ll * Bz * Hh;
        const size_t base_cn = base_hn + (size_t)Bz * Hh;
        out[base_hn + (size_t)b_e * Hh + kg] = hst;
        out[base_cn + (size_t)b_e * Hh + kg] = cst;
    }
}

// ---------------------------------------------------------------------------
extern "C" void kernel_launch(void* const* d_in, const int* in_sizes, int n_in,
                              void* d_out, int out_size)
{
    const float* x    = (const float*)d_in[0];
    const void*  pa   = (const void*)d_in[1];
    // d_in[2] = mask (unused by the reference computation)
    const float* h0   = (const float*)d_in[3];
    const float* c0   = (const float*)d_in[4];
    const float* rule = (const float*)d_in[5];
    const float* toke = (const float*)d_in[6];
    const float* Wih  = (const float*)d_in[7];
    const float* Whh  = (const float*)d_in[8];
    const float* bih  = (const float*)d_in[9];
    const float* bhh  = (const float*)d_in[10];
    float* out = (float*)d_out;

    fused_proj<<<dim3(64, 4, 3), 256>>>(rule, toke, x, Wih, bih, bhh,
                                        (const int*)pa);
    prep_w<<<512, 256>>>(Whh);
    prep_h0<<<8, 256>>>(h0);

    cudaFuncSetAttribute(lstm_mma,
                         cudaFuncAttributeMaxDynamicSharedMemorySize,
                         SMEM_BYTES);
    lstm_mma<<<NCTA, TPB, SMEM_BYTES>>>(c0, pa, toke, Wih, out);
}

// round 14
// speedup vs baseline: 2.4489x; 1.2939x over previous
#include <cuda_runtime.h>
#include <cuda_fp16.h>
#include <math.h>
#include <stdint.h>

// ---------------------------------------------------------------------------
// LSTMDecoder via mma.sync fp16 2-pass (tcgen05 unavailable: harness targets
// compute_103 without the 'a' suffix).
//
// lstm_mma: 128 persistent CTAs x 512 threads. Per CTA: 8 hidden units
// (32 gate rows x 64 batch). W_hh fp16 hi/lo slice resident in SMEM (129KB)
// all steps. Per step: 8 K-chunks of single-plane fp16 h streamed via
// cp.async double buffer; 16 warps = kw(4) x mi(2) x nj(2); 2-pass
// (Whi*h + Wlo*h) m16n8k16 fp16, fp32 regs; 4-way cross-kw reduce in SMEM;
// unit-fastest epilogue with gathers; split-counter barrier.
// R14 single variable vs R13: bf16 3-pass -> fp16 2-pass, h single plane
// (halves the L2 h stream that sits at the LTS cap, cuts MMA work 33%).
// ---------------------------------------------------------------------------

#define Bz    64
#define Hh    1024
#define Ll    128
#define G4    4096
#define KDIM  512
#define NCTA  128
#define TPB   512

__device__ float g_rp[256 * 4096];
__device__ float g_tp[256 * 4096];
__device__ float g_xp[64 * 4096];
__device__ __align__(16) unsigned char g_wimg[128u * 132096u];
__device__ __align__(16) unsigned short g_h16[2][65536];   // single fp16 plane
__device__ unsigned int g_ctr8[256];   // 8 counters at stride 32 (128B apart)
__device__ int          g_is64;

// ---- smem layout (bytes, dynamic) ----
#define OFF_WHI 0
#define OFF_WLO 66048
#define OFF_HB0 132096
#define OFF_HB1 149504
#define SMEM_BYTES 166912
#define W_STRIDE 2064       // 1024 fp16 * 2B + 16 pad
#define H_STRIDE 272        // 128 fp16 * 2B + 16 pad

// ---- helpers ---------------------------------------------------------------
__device__ __forceinline__ uint32_t smem_to_u32(const void* smem_ptr) {
    uint32_t addr;
    asm("{ .reg .u64 tmp; cvta.to.shared.u64 tmp, %1; cvt.u32.u64 %0, tmp; }"
        : "=r"(addr) : "l"(smem_ptr));
    return addr;
}

#define CP_ASYNC16(dst, src) \
    asm volatile("cp.async.cg.shared.global [%0], [%1], 16;" \
                 :: "r"((uint32_t)(dst)), "l"(src) : "memory")
#define CP_COMMIT() \
    asm volatile("cp.async.commit_group;" ::: "memory")
#define CP_WAIT0() \
    asm volatile("cp.async.wait_group 0;" ::: "memory")

__device__ __forceinline__ void ldsm4(uint32_t& r0, uint32_t& r1,
                                      uint32_t& r2, uint32_t& r3,
                                      uint32_t addr) {
    asm volatile(
        "ldmatrix.sync.aligned.m8n8.x4.shared.b16 {%0, %1, %2, %3}, [%4];"
        : "=r"(r0), "=r"(r1), "=r"(r2), "=r"(r3)
        : "r"(addr));
}

__device__ __forceinline__ void mma_f16(float& d0, float& d1, float& d2, float& d3,
                                        uint32_t a0, uint32_t a1, uint32_t a2, uint32_t a3,
                                        uint32_t b0, uint32_t b1) {
    asm volatile(
        "mma.sync.aligned.m16n8k16.row.col.f32.f16.f16.f32 "
        "{%0, %1, %2, %3}, {%4, %5, %6, %7}, {%8, %9}, {%0, %1, %2, %3};"
        : "+f"(d0), "+f"(d1), "+f"(d2), "+f"(d3)
        : "r"(a0), "r"(a1), "r"(a2), "r"(a3), "r"(b0), "r"(b1));
}

__device__ __forceinline__ unsigned short hbits(float v) {
    __half t = __float2half_rn(v);
    return *(unsigned short*)&t;
}
__device__ __forceinline__ float h2f(unsigned short b) {
    __half t = *(__half*)&b;
    return __half2float(t);
}
__device__ __forceinline__ float sigf(float x) {
    return 1.0f / (1.0f + __expf(-x));
}

// ---------------------------------------------------------------------------
// fused_proj: tables + counter reset + pa dtype sniff. grid (64,4,3), blk 256.
// ---------------------------------------------------------------------------
__global__ void fused_proj(const float* __restrict__ rule,
                           const float* __restrict__ toke,
                           const float* __restrict__ x,
                           const float* __restrict__ Wih,
                           const float* __restrict__ b1,
                           const float* __restrict__ b2,
                           const int*   __restrict__ pa32)
{
    const int z = blockIdx.z;
    const float* E;
    float* Out;
    int M;
    int colOff;
    int addBias = 0;
    if (z == 0)      { E = rule; Out = g_rp; M = 256; colOff = 512; }
    else if (z == 1) { E = toke; Out = g_tp; M = 256; colOff = 512; }
    else             { E = x;    Out = g_xp; M = 64;  colOff = 0; addBias = 1; }

    if (z == 2 && blockIdx.x == 0 && blockIdx.y == 0) {
        __shared__ int any_nz;
        if (threadIdx.x == 0) { any_nz = 0; }
        if (threadIdx.x < 8) g_ctr8[threadIdx.x * 32] = 0u;
        __syncthreads();
        if (threadIdx.x < 256 && pa32[threadIdx.x * 2 + 1] != 0)
            atomicAdd(&any_nz, 1);
        __syncthreads();
        if (threadIdx.x == 0) g_is64 = (any_nz == 0) ? 1 : 0;
    }
    if (blockIdx.y * 64 >= M) return;

    __shared__ float Es[64][17];
    __shared__ float Ws[64][17];

    const int i0 = blockIdx.y * 64;
    const int j0 = blockIdx.x * 64;
    const int t  = threadIdx.x;
    const int ty = t >> 4;
    const int tx = t & 15;

    float acc[4][4];
#pragma unroll
    for (int i = 0; i < 4; i++)
#pragma unroll
        for (int j = 0; j < 4; j++) acc[i][j] = 0.f;

    const int ii = t >> 2;
    const int a4 = (t & 3) * 4;

    for (int a0 = 0; a0 < KDIM; a0 += 16) {
        float4 ev = make_float4(0.f, 0.f, 0.f, 0.f);
        if (i0 + ii < M)
            ev = *(const float4*)(E + (size_t)(i0 + ii) * KDIM + a0 + a4);
        Es[ii][a4 + 0] = ev.x;
        Es[ii][a4 + 1] = ev.y;
        Es[ii][a4 + 2] = ev.z;
        Es[ii][a4 + 3] = ev.w;

        float4 wv = *(const float4*)(Wih + (size_t)(j0 + ii) * 1024 + colOff + a0 + a4);
        Ws[ii][a4 + 0] = wv.x;
        Ws[ii][a4 + 1] = wv.y;
        Ws[ii][a4 + 2] = wv.z;
        Ws[ii][a4 + 3] = wv.w;
        __syncthreads();

#pragma unroll
        for (int aa = 0; aa < 16; aa++) {
            float av[4];
            float bv[4];
#pragma unroll
            for (int r2 = 0; r2 < 4; r2++) av[r2] = Es[ty * 4 + r2][aa];
#pragma unroll
            for (int r2 = 0; r2 < 4; r2++) bv[r2] = Ws[tx * 4 + r2][aa];
#pragma unroll
            for (int i = 0; i < 4; i++)
#pragma unroll
                for (int j = 0; j < 4; j++) acc[i][j] = fmaf(av[i], bv[j], acc[i][j]);
        }
        __syncthreads();
    }

#pragma unroll
    for (int i = 0; i < 4; i++) {
        int gi = i0 + ty * 4 + i;
        if (gi >= M) continue;
#pragma unroll
        for (int j = 0; j < 4; j++) {
            int gj = j0 + tx * 4 + j;
            float v = acc[i][j];
            if (addBias) v += b1[gj] + b2[gj];
            Out[(size_t)gi * G4 + gj] = v;
        }
    }
}

// ---------------------------------------------------------------------------
// prep_w: bake W_hh into per-CTA fp16 hi/lo images (SMEM layout, stride 2064).
// ---------------------------------------------------------------------------
__global__ void prep_w(const float* __restrict__ Whh)
{
    const int id   = blockIdx.x * 256 + threadIdx.x;
    const int g    = id >> 10;
    const int r    = (id >> 5) & 31;
    const int kseg = id & 31;
    const int k0   = kseg * 32;
    const int gate = r >> 3;
    const int u    = r & 7;

    const float* src = Whh + (size_t)(gate * 1024 + g * 8 + u) * 1024 + k0;
    unsigned char* dhi = g_wimg + (size_t)g * 132096 + r * W_STRIDE + k0 * 2;
    unsigned char* dlo = dhi + 66048;

#pragma unroll
    for (int j = 0; j < 4; j++) {
        float4 va = *(const float4*)(src + j * 8);
        float4 vb = *(const float4*)(src + j * 8 + 4);
        float v[8];
        v[0] = va.x; v[1] = va.y; v[2] = va.z; v[3] = va.w;
        v[4] = vb.x; v[5] = vb.y; v[6] = vb.z; v[7] = vb.w;
        unsigned int hw[4];
        unsigned int lw[4];
#pragma unroll
        for (int q = 0; q < 4; q++) {
            unsigned short h0 = hbits(v[2 * q]);
            unsigned short l0 = hbits(v[2 * q] - h2f(h0));
            unsigned short h1 = hbits(v[2 * q + 1]);
            unsigned short l1 = hbits(v[2 * q + 1] - h2f(h1));
            hw[q] = (unsigned)h0 | ((unsigned)h1 << 16);
            lw[q] = (unsigned)l0 | ((unsigned)l1 << 16);
        }
        *(uint4*)(dhi + j * 16) = make_uint4(hw[0], hw[1], hw[2], hw[3]);
        *(uint4*)(dlo + j * 16) = make_uint4(lw[0], lw[1], lw[2], lw[3]);
    }
}

// ---------------------------------------------------------------------------
// prep_h0: bake initial h into g_h16 parity 0 (single fp16 plane).
// ---------------------------------------------------------------------------
__global__ void prep_h0(const float* __restrict__ h0)
{
    const int id = blockIdx.x * 256 + threadIdx.x;
    if (id >= 2048) return;
    const int b    = id >> 5;
    const int kseg = id & 31;
    const int k0   = kseg * 32;

    const float* src = h0 + (size_t)b * 1024 + k0;
    unsigned short* dhi = &g_h16[0][b * 1024 + k0];

#pragma unroll
    for (int j = 0; j < 4; j++) {
        float4 va = *(const float4*)(src + j * 8);
        float4 vb = *(const float4*)(src + j * 8 + 4);
        float v[8];
        v[0] = va.x; v[1] = va.y; v[2] = va.z; v[3] = va.w;
        v[4] = vb.x; v[5] = vb.y; v[6] = vb.z; v[7] = vb.w;
        unsigned int hw[4];
#pragma unroll
        for (int q = 0; q < 4; q++) {
            hw[q] = (unsigned)hbits(v[2 * q]) | ((unsigned)hbits(v[2 * q + 1]) << 16);
        }
        *(uint4*)(dhi + j * 8) = make_uint4(hw[0], hw[1], hw[2], hw[3]);
    }
}

// ---------------------------------------------------------------------------
// lstm_mma: persistent 128-CTA x 512-thread mma.sync recurrence.
// ---------------------------------------------------------------------------
__global__ void __launch_bounds__(TPB, 1)
lstm_mma(const float* __restrict__ c0,
         const void*  __restrict__ pa_raw,
         const float* __restrict__ tok_embed,
         const float* __restrict__ W_ih,
         float* __restrict__ out)
{
    extern __shared__ unsigned char smem[];
    const uint32_t sb = smem_to_u32(smem);
    const int tid  = threadIdx.x;
    const int wid  = tid >> 5;
    const int lane = tid & 31;
    const int g    = blockIdx.x;
    const int is64 = g_is64;

    // ---- one-time W image copy into SMEM ----
    {
        const unsigned char* wsrc = g_wimg + (size_t)g * 132096;
        for (int i = tid; i < 8256; i += TPB) {
            CP_ASYNC16(sb + OFF_WHI + i * 16, wsrc + (size_t)i * 16);
        }
        CP_COMMIT();
        CP_WAIT0();
        __syncthreads();
    }

    // ---- epilogue identity: 1 (b, u) pair per thread, unit-fastest ----
    const int u_e = tid & 7;
    const int b_e = tid >> 3;          // 0..63
    const int kg  = g * 8 + u_e;
    float cst = c0[(size_t)b_e * Hh + kg];
    float hst = 0.f;

    // ---- GEMM identity: 16 warps = kw(4) x mi(2) x nj(2) ----
    const int kw = wid >> 2;           // 0..3  (32 kk each within a chunk)
    const int mi = (wid >> 1) & 1;     // 0..1  (16 gate rows)
    const int nj = wid & 1;            // 0..1  (32 batches)
    const uint32_t aoff = (uint32_t)((mi * 16 + (lane & 15)) * W_STRIDE
                                     + ((lane & 16) ? 16 : 0));
    const uint32_t boff = (uint32_t)((nj * 32 + (lane & 15)) * H_STRIDE
                                     + ((lane & 16) ? 16 : 0));

    // staging identity: row = tid>>3 (0..63), seg = tid&7 (16 kk = 32B each)
    const int sg_row = tid >> 3;
    const int sg_seg = tid & 7;

    float* smemD = (float*)(smem + OFF_HB0);   // [kw 4][32][65] fp32 overlay

#pragma unroll 1
    for (int l = 0; l < Ll; l++) {
        const unsigned short* hsrc = &g_h16[l & 1][0];

        // prologue: issue chunk 0 into HB0
        {
            const unsigned short* srcH = hsrc + sg_row * 1024 + sg_seg * 16;
            const uint32_t dstH = sb + OFF_HB0 + sg_row * H_STRIDE + sg_seg * 32;
            CP_ASYNC16(dstH,      srcH);
            CP_ASYNC16(dstH + 16, srcH + 8);
            CP_COMMIT();
        }

        float acc[16];
#pragma unroll
        for (int i = 0; i < 16; i++) acc[i] = 0.f;

#pragma unroll 1
        for (int c = 0; c < 8; c++) {
            CP_WAIT0();
            __syncthreads();
            if (c < 7) {
                const unsigned short* srcH = hsrc + sg_row * 1024 + (c + 1) * 128 + sg_seg * 16;
                const uint32_t hb = (c & 1) ? OFF_HB0 : OFF_HB1;
                const uint32_t dstH = sb + hb + sg_row * H_STRIDE + sg_seg * 32;
                CP_ASYNC16(dstH,      srcH);
                CP_ASYNC16(dstH + 16, srcH + 8);
                CP_COMMIT();
            }

            const uint32_t hb   = (c & 1) ? OFF_HB1 : OFF_HB0;
            const uint32_t bHi  = sb + hb + boff + kw * 64;
            const uint32_t aHiB = sb + OFF_WHI + aoff + c * 256 + kw * 64;
            const uint32_t aLoB = aHiB + 66048;

#pragma unroll
            for (int ks = 0; ks < 2; ks++) {
                uint32_t ah0, ah1, ah2, ah3;
                uint32_t al0, al1, al2, al3;
                uint32_t bh0, bh1, bh2, bh3, bh4, bh5, bh6, bh7;
                ldsm4(ah0, ah1, ah2, ah3, aHiB + ks * 32);
                ldsm4(al0, al1, al2, al3, aLoB + ks * 32);
                ldsm4(bh0, bh1, bh2, bh3, bHi + ks * 32);
                ldsm4(bh4, bh5, bh6, bh7, bHi + 16 * H_STRIDE + ks * 32);
                // group 0: cols +0..7   {bh0,bh2}
                mma_f16(acc[0],  acc[1],  acc[2],  acc[3],  ah0, ah1, ah2, ah3, bh0, bh2);
                mma_f16(acc[0],  acc[1],  acc[2],  acc[3],  al0, al1, al2, al3, bh0, bh2);
                // group 1: cols +8..15  {bh1,bh3}
                mma_f16(acc[4],  acc[5],  acc[6],  acc[7],  ah0, ah1, ah2, ah3, bh1, bh3);
                mma_f16(acc[4],  acc[5],  acc[6],  acc[7],  al0, al1, al2, al3, bh1, bh3);
                // group 2: cols +16..23 {bh4,bh6}
                mma_f16(acc[8],  acc[9],  acc[10], acc[11], ah0, ah1, ah2, ah3, bh4, bh6);
                mma_f16(acc[8],  acc[9],  acc[10], acc[11], al0, al1, al2, al3, bh4, bh6);
                // group 3: cols +24..31 {bh5,bh7}
                mma_f16(acc[12], acc[13], acc[14], acc[15], ah0, ah1, ah2, ah3, bh5, bh7);
                mma_f16(acc[12], acc[13], acc[14], acc[15], al0, al1, al2, al3, bh5, bh7);
            }
        }
        __syncthreads();   // computes done; HB0/HB1 free for D overlay

        // ---- write D fragments to smemD[kw][32][65] ----
        {
            const int lr = lane >> 2;
            const int lc = (lane & 3) * 2;
            const int row0 = mi * 16 + lr;
            float* dk = smemD + kw * 2080;
#pragma unroll
            for (int s = 0; s < 4; s++) {
                const int col = nj * 32 + s * 8 + lc;
                dk[row0 * 65 + col]           = acc[s * 4 + 0];
                dk[row0 * 65 + col + 1]       = acc[s * 4 + 1];
                dk[(row0 + 8) * 65 + col]     = acc[s * 4 + 2];
                dk[(row0 + 8) * 65 + col + 1] = acc[s * 4 + 3];
            }
        }
        __syncthreads();

        // ---- epilogue: 1 (b, u) pair per thread (unit-fastest) ----
        {
            unsigned short* hdst = &g_h16[(l + 1) & 1][0];
            const size_t pidx = ((size_t)l * Bz + b_e) * 3;
            long long ridx;
            long long tidx;
            if (is64) {
                const long long* pp = (const long long*)pa_raw;
                ridx = pp[pidx];
                tidx = pp[pidx + 1];
            } else {
                const int* pp = (const int*)pa_raw;
                ridx = (long long)pp[pidx];
                tidx = (long long)pp[pidx + 1];
            }
            float gv[4];
#pragma unroll
            for (int gt = 0; gt < 4; gt++) {
                const int row = gt * 8 + u_e;
                float pre = smemD[row * 65 + b_e]
                          + smemD[2080 + row * 65 + b_e]
                          + smemD[4160 + row * 65 + b_e]
                          + smemD[6240 + row * 65 + b_e];
                const int gidx = gt * 1024 + kg;
                float xgv = g_xp[(size_t)b_e * G4 + gidx];
                if (ridx >= 0 && ridx < 256) {
                    xgv += g_rp[(size_t)ridx * G4 + gidx];
                }
                if (tidx >= 0 && tidx < 256) {
                    xgv += g_tp[(size_t)tidx * G4 + gidx];
                } else if (tidx >= 256 && tidx < 32000) {
                    const float* te = tok_embed + (size_t)tidx * KDIM;
                    const float* wa = W_ih + (size_t)gidx * 1024 + 512;
                    float d = 0.f;
                    for (int a = 0; a < KDIM; a++) {
                        d = fmaf(te[a], wa[a], d);
                    }
                    xgv += d;
                }
                gv[gt] = pre + xgv;
            }
            const float c1 = sigf(gv[1]) * cst + sigf(gv[0]) * tanhf(gv[2]);
            const float h1 = sigf(gv[3]) * tanhf(c1);
            cst = c1;
            hst = h1;
            out[((size_t)l * Bz + b_e) * Hh + kg] = h1;

            hdst[b_e * 1024 + kg] = hbits(h1);
        }

        // ---- device-wide barrier: 8 split counters, 16 arrivals each ----
        __threadfence();
        __syncthreads();
        if (tid == 0) {
            atomicAdd(&g_ctr8[(g & 7) * 32], 1u);
        }
        if (tid < 8) {
            const unsigned tgt = (unsigned)(l + 1) * 16u;
            while (*(volatile unsigned int*)&g_ctr8[tid * 32] < tgt) {
                __nanosleep(32);
            }
        }
        __syncthreads();
    }

    // ---- final h_n, c_n ----
    {
        const size_t base_hn = (size_t)Ll * Bz * Hh;
        const size_t base_cn = base_hn + (size_t)Bz * Hh;
        out[base_hn + (size_t)b_e * Hh + kg] = hst;
        out[base_cn + (size_t)b_e * Hh + kg] = cst;
    }
}

// ---------------------------------------------------------------------------
extern "C" void kernel_launch(void* const* d_in, const int* in_sizes, int n_in,
                              void* d_out, int out_size)
{
    const float* x    = (const float*)d_in[0];
    const void*  pa   = (const void*)d_in[1];
    // d_in[2] = mask (unused by the reference computation)
    const float* h0   = (const float*)d_in[3];
    const float* c0   = (const float*)d_in[4];
    const float* rule = (const float*)d_in[5];
    const float* toke = (const float*)d_in[6];
    const float* Wih  = (const float*)d_in[7];
    const float* Whh  = (const float*)d_in[8];
    const float* bih  = (const float*)d_in[9];
    const float* bhh  = (const float*)d_in[10];
    float* out = (float*)d_out;

    fused_proj<<<dim3(64, 4, 3), 256>>>(rule, toke, x, Wih, bih, bhh,
                                        (const int*)pa);
    prep_w<<<512, 256>>>(Whh);
    prep_h0<<<8, 256>>>(h0);

    cudaFuncSetAttribute(lstm_mma,
                         cudaFuncAttributeMaxDynamicSharedMemorySize,
                         SMEM_BYTES);
    lstm_mma<<<NCTA, TPB, SMEM_BYTES>>>(c0, pa, toke, Wih, out);
}